// round 1
// baseline (speedup 1.0000x reference)
#include <cuda_runtime.h>
#include <cuda_bf16.h>
#include <math.h>
#include <float.h>

// ---------------------------------------------------------------------------
// SocialTrans: T=16, N=64, NN=32, D=512, H=8, DK=64, DFF=2048, L=2
// ---------------------------------------------------------------------------
#define T_ 16
#define N_ 64
#define NN_ 32
#define D_ 512
#define H_ 8
#define DK_ 64
#define DFF_ 2048
#define L_ 2
#define NPAIR (N_*NN_)          // 2048
#define NTOKB (NPAIR*T_)        // 32768  neighbor tokens
#define NTOKS (N_*T_)           // 1024   self tokens

// ------------------------- device scratch (static, no allocs) --------------
__device__ float g_xf  [T_*N_*4];
__device__ float g_nf  [T_*N_*NN_*3];
__device__ unsigned char g_mask[NPAIR*T_];
__device__ float g_pe  [T_*D_];
__device__ float g_xe  [NTOKS*D_];
__device__ float g_ne  [NTOKB*D_];
__device__ float g_Q   [NTOKB*D_];
__device__ float g_K   [NTOKB*D_];
__device__ float g_V   [NTOKB*D_];
__device__ float g_ctx [NTOKB*D_];
__device__ float g_tmpM[NTOKB*D_];
__device__ float g_res [NTOKB*D_];
__device__ float g_hidM[NTOKB*DFF_];
__device__ float g_attn[NPAIR*H_*T_*T_];
__device__ float g_attint[N_*H_*T_*T_];
__device__ float g_attself[N_*T_*T_];
__device__ float g_si  [NTOKS*H_*D_];
__device__ float g_xnew[NTOKS*D_];
__device__ float g_hidS[NTOKS*DFF_];
__device__ float g_tmpS[NTOKS*D_];

// ------------------------- helpers -----------------------------------------
__device__ __forceinline__ float n2n(float v) {
    if (isnan(v)) return 0.0f;
    if (isinf(v)) return v > 0.0f ? 3.4028235e38f : -3.4028235e38f;
    return v;
}

// ------------------------- feature kernel -----------------------------------
__global__ void feat_kernel(const float* __restrict__ x, const float* __restrict__ nb,
                            float* __restrict__ xf, float* __restrict__ nf,
                            unsigned char* __restrict__ mask) {
    int idx = blockIdx.x * blockDim.x + threadIdx.x;   // t,n,nn
    if (idx >= T_*N_*NN_) return;
    int nn = idx & (NN_-1);
    int rem = idx >> 5;
    int n  = rem & (N_-1);
    int t  = rem >> 6;
    const float* xr = x + ((size_t)t*N_ + n)*6;
    float px = xr[0], py = xr[1];
    float vx, vy;
    if (t == 0) {
        const float* x1 = x + ((size_t)1*N_ + n)*6;
        vx = x1[2]; vy = x1[3];
    } else {
        const float* xp = x + ((size_t)(t-1)*N_ + n)*6;
        vx = px - xp[0]; vy = py - xp[1];
    }
    const float* nr = nb + (((size_t)t*N_ + n)*NN_ + nn)*4;
    float dpx = nr[0]-px, dpy = nr[1]-py;
    float dvx = nr[2]-vx, dvy = nr[3]-vy;
    float dist = sqrtf(dpx*dpx + dpy*dpy);
    mask[(n*NN_ + nn)*T_ + t] = (dist <= 2.0f) ? 1 : 0;
    float nv = sqrtf(vx*vx + vy*vy);
    float bearing = (dpx*vx + dpy*vy) / (dist*nv);
    if (isnan(bearing)) bearing = 0.0f;
    float ndv = sqrtf(dvx*dvx + dvy*dvy);
    float tau = -(dpx*dvx + dpy*dvy) / ndv;
    if (isnan(tau)) tau = 0.0f;
    tau = fminf(fmaxf(tau, 0.0f), 7.0f);
    float mxx = dpx + tau*dvx, myy = dpy + tau*dvy;
    float mpd = sqrtf(mxx*mxx + myy*myy);
    float* o = nf + (size_t)idx*3;
    o[0] = n2n(dist); o[1] = n2n(bearing); o[2] = n2n(mpd);
    if (nn == 0) {
        float vel = sqrtf(xr[2]*xr[2] + xr[3]*xr[3]);
        float ang = atanf(xr[5]/xr[4]);
        float* xo = xf + ((size_t)t*N_ + n)*4;
        xo[0] = n2n(xr[0]); xo[1] = n2n(xr[1]); xo[2] = n2n(vel); xo[3] = n2n(ang);
    }
}

// ------------------------- positional encoding -------------------------------
__global__ void pe_kernel(float* __restrict__ pe) {
    int i = blockIdx.x * blockDim.x + threadIdx.x;
    if (i >= T_*D_) return;
    int t = i >> 9, d = i & (D_-1);
    double expo = (double)(d & ~1) / (double)D_;
    float div = (float)exp(expo * 9.210340371976184);  // ln(10000)
    float arg = (float)t * div;                         // f32 product like JAX
    pe[i] = (d & 1) ? (float)cos((double)arg) : (float)sin((double)arg);
}

// ------------------------- embeddings ----------------------------------------
__global__ void xemb_kernel(const float* __restrict__ xf, const float* __restrict__ Wx,
                            const float* __restrict__ bx, const float* __restrict__ pe,
                            float* __restrict__ xe) {
    int i = blockIdx.x * blockDim.x + threadIdx.x;     // (t*N+n)*D + d
    if (i >= NTOKS*D_) return;
    int d = i & (D_-1);
    int tok = i >> 9;
    int t = tok >> 6, n = tok & (N_-1);
    const float* f = xf + (size_t)tok*4;
    float acc = bx[d] + pe[t*D_ + d];
    #pragma unroll
    for (int k = 0; k < 4; k++) acc = fmaf(f[k], Wx[k*D_ + d], acc);
    xe[((size_t)(n*T_ + t))*D_ + d] = acc;             // stored (N,T,D)
}

__global__ void nemb_kernel(const float* __restrict__ nf, const float* __restrict__ Wn,
                            const float* __restrict__ bn, const float* __restrict__ pe,
                            float* __restrict__ ne) {
    size_t i = (size_t)blockIdx.x * blockDim.x + threadIdx.x;
    if (i >= (size_t)NTOKB*D_) return;
    int d = (int)(i & (D_-1));
    int tok = (int)(i >> 9);                           // (t,n,nn)
    int nn = tok & (NN_-1);
    int rem = tok >> 5;
    int n = rem & (N_-1);
    int t = rem >> 6;
    const float* f = nf + (size_t)tok*3;
    float acc = bn[d] + pe[t*D_ + d];
    acc = fmaf(f[0], Wn[d], acc);
    acc = fmaf(f[1], Wn[D_ + d], acc);
    acc = fmaf(f[2], Wn[2*D_ + d], acc);
    ne[(((size_t)(n*NN_ + nn))*T_ + t)*D_ + d] = acc;  // stored (N,NN,T,D)
}

// ------------------------- SGEMM 128x128x8 ----------------------------------
// C(M,N) = op( A(M,K) @ B(K,N) ), optional relu.  M%128==0, N%128==0, K%8==0.
__global__ void __launch_bounds__(256)
sgemm_kernel(const float* __restrict__ A, const float* __restrict__ B,
             float* __restrict__ C, int M, int N, int K, int relu) {
    __shared__ float As[8][128];
    __shared__ float Bs[8][128];
    int bx = blockIdx.x, by = blockIdx.y;
    int tid = threadIdx.x;
    int tx = tid & 15, ty = tid >> 4;
    const float* Ab = A + (size_t)by*128*K;
    const float* Bb = B + (size_t)bx*128;
    int arow = tid >> 1, acol = (tid & 1)*4;
    int brow = tid >> 5, bcol = (tid & 31)*4;
    float acc[8][8];
    #pragma unroll
    for (int i = 0; i < 8; i++)
        #pragma unroll
        for (int j = 0; j < 8; j++) acc[i][j] = 0.0f;

    for (int k0 = 0; k0 < K; k0 += 8) {
        float4 av = *(const float4*)(Ab + (size_t)arow*K + k0 + acol);
        As[acol+0][arow] = av.x;
        As[acol+1][arow] = av.y;
        As[acol+2][arow] = av.z;
        As[acol+3][arow] = av.w;
        float4 bv = *(const float4*)(Bb + (size_t)(k0+brow)*N + bcol);
        *(float4*)&Bs[brow][bcol] = bv;
        __syncthreads();
        #pragma unroll
        for (int k = 0; k < 8; k++) {
            float a[8], b[8];
            #pragma unroll
            for (int i = 0; i < 8; i++) a[i] = As[k][ty*8 + i];
            #pragma unroll
            for (int j = 0; j < 8; j++) b[j] = Bs[k][tx*8 + j];
            #pragma unroll
            for (int i = 0; i < 8; i++)
                #pragma unroll
                for (int j = 0; j < 8; j++)
                    acc[i][j] = fmaf(a[i], b[j], acc[i][j]);
        }
        __syncthreads();
    }
    #pragma unroll
    for (int i = 0; i < 8; i++) {
        size_t row = (size_t)by*128 + ty*8 + i;
        float* Cr = C + row*N + bx*128 + tx*8;
        #pragma unroll
        for (int j = 0; j < 8; j++) {
            float v = acc[i][j];
            if (relu) v = fmaxf(v, 0.0f);
            Cr[j] = v;
        }
    }
}

static inline void sgemm(const float* A, const float* B, float* C,
                         int M, int N, int K, int relu) {
    dim3 grid(N/128, M/128);
    sgemm_kernel<<<grid, 256>>>(A, B, C, M, N, K, relu);
}

// ------------------------- neighbor attention --------------------------------
// block per (pair, h): scores->mask->softmax->ctx; attn saved for mean reduce.
__global__ void attn_kernel(const float* __restrict__ Q, const float* __restrict__ K,
                            const float* __restrict__ V, const unsigned char* __restrict__ mask,
                            float* __restrict__ ctx, float* __restrict__ attn_out) {
    int b = blockIdx.x;              // pair*8 + h
    int h = b & (H_-1);
    int pair = b >> 3;
    int tid = threadIdx.x;           // 256
    __shared__ float q[16*68], k[16*68], v[16*68];
    __shared__ float at[16*17];
    size_t base = (size_t)pair*T_*D_ + h*DK_;
    for (int i = tid; i < 16*64; i += 256) {
        int t = i >> 6, d = i & 63;
        q[t*68+d] = Q[base + (size_t)t*D_ + d];
        k[t*68+d] = K[base + (size_t)t*D_ + d];
        v[t*68+d] = V[base + (size_t)t*D_ + d];
    }
    __syncthreads();
    int qt = tid >> 4, kt = tid & 15;
    float s = 0.0f;
    #pragma unroll
    for (int d = 0; d < 64; d++) s = fmaf(q[qt*68+d], k[kt*68+d], s);
    s *= 0.125f;
    if (!mask[pair*T_ + qt]) s = -1e9f;
    float mx = s;
    #pragma unroll
    for (int o = 8; o; o >>= 1) mx = fmaxf(mx, __shfl_xor_sync(0xffffffffu, mx, o));
    float e = expf(s - mx);
    float sum = e;
    #pragma unroll
    for (int o = 8; o; o >>= 1) sum += __shfl_xor_sync(0xffffffffu, sum, o);
    float a = e / sum;
    at[qt*17 + kt] = a;
    attn_out[(size_t)b*256 + qt*16 + kt] = a;
    __syncthreads();
    for (int i = tid; i < 16*64; i += 256) {
        int t = i >> 6, d = i & 63;
        float acc = 0.0f;
        #pragma unroll
        for (int kk = 0; kk < 16; kk++) acc = fmaf(at[t*17+kk], v[kk*68+d], acc);
        ctx[base + (size_t)t*D_ + d] = acc;
    }
}

// attn.mean over nn  (deterministic, no atomics)
__global__ void attmean_kernel(const float* __restrict__ attn, float* __restrict__ attint) {
    int i = blockIdx.x * blockDim.x + threadIdx.x;   // N*H*256
    if (i >= N_*H_*256) return;
    int qk = i & 255;
    int h  = (i >> 8) & (H_-1);
    int n  = i >> 11;
    float s = 0.0f;
    #pragma unroll 4
    for (int nn = 0; nn < NN_; nn++)
        s += attn[(((size_t)(n*NN_ + nn)*H_ + h)*256) + qk];
    attint[i] = s * (1.0f/32.0f);
}

// ------------------------- add + layernorm -----------------------------------
__global__ void add_ln_kernel(const float* __restrict__ X, const float* __restrict__ R,
                              const float* __restrict__ g, const float* __restrict__ b,
                              float* __restrict__ out) {
    int row = blockIdx.x, tid = threadIdx.x;   // 256 threads, D=512
    size_t off = (size_t)row*D_;
    float x0 = X[off+tid]     + R[off+tid];
    float x1 = X[off+256+tid] + R[off+256+tid];
    __shared__ float red[8], red2[8];
    float s = x0 + x1;
    #pragma unroll
    for (int o = 16; o; o >>= 1) s += __shfl_xor_sync(0xffffffffu, s, o);
    if ((tid & 31) == 0) red[tid >> 5] = s;
    __syncthreads();
    float tot = 0.0f;
    #pragma unroll
    for (int i = 0; i < 8; i++) tot += red[i];
    float m = tot * (1.0f/512.0f);
    float d0 = x0 - m, d1 = x1 - m;
    float vs = d0*d0 + d1*d1;
    #pragma unroll
    for (int o = 16; o; o >>= 1) vs += __shfl_xor_sync(0xffffffffu, vs, o);
    if ((tid & 31) == 0) red2[tid >> 5] = vs;
    __syncthreads();
    float vtot = 0.0f;
    #pragma unroll
    for (int i = 0; i < 8; i++) vtot += red2[i];
    float inv = 1.0f / sqrtf(vtot * (1.0f/512.0f) + 1e-5f);
    out[off+tid]     = d0*inv*g[tid]     + b[tid];
    out[off+256+tid] = d1*inv*g[tid+256] + b[tid+256];
}

// ------------------------- self attention (x_emb @ x_emb^T) ------------------
__global__ void attself_kernel(const float* __restrict__ xe, float* __restrict__ attself) {
    int n = blockIdx.x;
    int tid = threadIdx.x;            // 256
    __shared__ float xs[16*516];
    for (int i = tid; i < 16*D_; i += 256) {
        int t = i >> 9, d = i & (D_-1);
        xs[t*516 + d] = xe[((size_t)(n*T_ + t))*D_ + d];
    }
    __syncthreads();
    int q = tid >> 4, k = tid & 15;
    float s = 0.0f;
    for (int d = 0; d < D_; d++) s = fmaf(xs[q*516+d], xs[k*516+d], s);
    s *= 0.04419417382415922f;        // 1/sqrt(512)
    float mx = s;
    #pragma unroll
    for (int o = 8; o; o >>= 1) mx = fmaxf(mx, __shfl_xor_sync(0xffffffffu, mx, o));
    float e = expf(s - mx);
    float sum = e;
    #pragma unroll
    for (int o = 8; o; o >>= 1) sum += __shfl_xor_sync(0xffffffffu, sum, o);
    attself[(size_t)n*256 + q*16 + k] = e / sum;
}

// ------------------------- si = (att_self + f*att_inter) @ x_emb -------------
__global__ void si_kernel(const float* __restrict__ xe, const float* __restrict__ attself,
                          const float* __restrict__ attint, const float* __restrict__ att_factor,
                          float* __restrict__ si) {
    int n = blockIdx.x >> 4;
    int q = blockIdx.x & 15;
    int tid = threadIdx.x;            // 512
    __shared__ float xs[16*512];
    __shared__ float arow[H_*16];
    float factor = att_factor[0];
    for (int i = tid; i < 16*D_; i += 512) xs[i] = xe[(size_t)n*T_*D_ + i];
    if (tid < H_*16) {
        int h = tid >> 4, t = tid & 15;
        arow[tid] = attself[(size_t)n*256 + q*16 + t]
                  + factor * attint[((n*H_ + h)*16 + q)*16 + t];
    }
    __syncthreads();
    int d = tid;
    #pragma unroll
    for (int h = 0; h < H_; h++) {
        float acc = 0.0f;
        #pragma unroll
        for (int t = 0; t < 16; t++) acc = fmaf(arow[h*16+t], xs[t*512 + d], acc);
        si[((size_t)(n*T_ + q))*(H_*D_) + h*D_ + d] = acc;
    }
}

// ------------------------- prediction head -----------------------------------
__global__ void pred_kernel(const float* __restrict__ xe, const float* __restrict__ Wp,
                            const float* __restrict__ bp, float* __restrict__ out) {
    int idx = blockIdx.x * blockDim.x + threadIdx.x;   // n*16*2
    if (idx >= N_*T_*2) return;
    int c = idx & 1;
    int t = (idx >> 1) & 15;
    int n = idx >> 5;
    float acc = bp[c];
    const float* xr = xe + ((size_t)(n*T_ + t))*D_;
    for (int d = 0; d < D_; d++) acc = fmaf(xr[d], Wp[d*2 + c], acc);
    for (int p = 0; p < 20; p++)
        out[(((size_t)p*T_ + t)*N_ + n)*2 + c] = acc;
}

// ---------------------------------------------------------------------------
extern "C" void kernel_launch(void* const* d_in, const int* in_sizes, int n_in,
                              void* d_out, int out_size) {
    const float* x        = (const float*)d_in[0];
    const float* neighbor = (const float*)d_in[1];
    const float* att_fac  = (const float*)d_in[2];
    const float* Wx       = (const float*)d_in[3];
    const float* bx       = (const float*)d_in[4];
    const float* Wn       = (const float*)d_in[5];
    const float* bn       = (const float*)d_in[6];
    const float* Wpred    = (const float*)d_in[7];
    const float* bpred    = (const float*)d_in[8];
    const float* WQ       = (const float*)d_in[9];
    const float* WK       = (const float*)d_in[10];
    const float* WV       = (const float*)d_in[11];
    const float* Wfc      = (const float*)d_in[12];
    const float* mha_g    = (const float*)d_in[13];
    const float* mha_b    = (const float*)d_in[14];
    const float* WSI      = (const float*)d_in[15];
    const float* ffs_w1   = (const float*)d_in[16];
    const float* ffs_w2   = (const float*)d_in[17];
    const float* ffs_g    = (const float*)d_in[18];
    const float* ffs_b    = (const float*)d_in[19];
    const float* ffi_w1   = (const float*)d_in[20];
    const float* ffi_w2   = (const float*)d_in[21];
    const float* ffi_g    = (const float*)d_in[22];
    const float* ffi_b    = (const float*)d_in[23];
    float* out = (float*)d_out;

    static float *pxf=0,*pnf=0,*ppe=0,*pxe=0,*pne=0,*pQ=0,*pK=0,*pV=0,*pctx=0,
                 *ptmpM=0,*pres=0,*phidM=0,*pattn=0,*pattint=0,*pattself=0,
                 *psi=0,*pxnew=0,*phidS=0,*ptmpS=0;
    static unsigned char* pmask=0;
    if (!pxf) {
        cudaGetSymbolAddress((void**)&pxf, g_xf);
        cudaGetSymbolAddress((void**)&pnf, g_nf);
        cudaGetSymbolAddress((void**)&pmask, g_mask);
        cudaGetSymbolAddress((void**)&ppe, g_pe);
        cudaGetSymbolAddress((void**)&pxe, g_xe);
        cudaGetSymbolAddress((void**)&pne, g_ne);
        cudaGetSymbolAddress((void**)&pQ, g_Q);
        cudaGetSymbolAddress((void**)&pK, g_K);
        cudaGetSymbolAddress((void**)&pV, g_V);
        cudaGetSymbolAddress((void**)&pctx, g_ctx);
        cudaGetSymbolAddress((void**)&ptmpM, g_tmpM);
        cudaGetSymbolAddress((void**)&pres, g_res);
        cudaGetSymbolAddress((void**)&phidM, g_hidM);
        cudaGetSymbolAddress((void**)&pattn, g_attn);
        cudaGetSymbolAddress((void**)&pattint, g_attint);
        cudaGetSymbolAddress((void**)&pattself, g_attself);
        cudaGetSymbolAddress((void**)&psi, g_si);
        cudaGetSymbolAddress((void**)&pxnew, g_xnew);
        cudaGetSymbolAddress((void**)&phidS, g_hidS);
        cudaGetSymbolAddress((void**)&ptmpS, g_tmpS);
    }

    // features + PE + embeddings
    feat_kernel<<<(T_*N_*NN_+255)/256, 256>>>(x, neighbor, pxf, pnf, pmask);
    pe_kernel<<<(T_*D_+255)/256, 256>>>(ppe);
    xemb_kernel<<<(NTOKS*D_+255)/256, 256>>>(pxf, Wx, bx, ppe, pxe);
    nemb_kernel<<<(int)(((size_t)NTOKB*D_+255)/256), 256>>>(pnf, Wn, bn, ppe, pne);

    for (int l = 0; l < L_; l++) {
        const float* WQl  = WQ  + (size_t)l*D_*D_;
        const float* WKl  = WK  + (size_t)l*D_*D_;
        const float* WVl  = WV  + (size_t)l*D_*D_;
        const float* Wfcl = Wfc + (size_t)l*D_*D_;
        const float* WSIl = WSI + (size_t)l*(H_*D_)*D_;

        sgemm(pne, WQl, pQ, NTOKB, D_, D_, 0);
        sgemm(pne, WKl, pK, NTOKB, D_, D_, 0);
        sgemm(pne, WVl, pV, NTOKB, D_, D_, 0);

        attn_kernel<<<NPAIR*H_, 256>>>(pQ, pK, pV, pmask, pctx, pattn);
        attmean_kernel<<<(N_*H_*256+255)/256, 256>>>(pattn, pattint);

        sgemm(pctx, Wfcl, ptmpM, NTOKB, D_, D_, 0);
        add_ln_kernel<<<NTOKB, 256>>>(ptmpM, pne, mha_g + l*D_, mha_b + l*D_, pres);

        attself_kernel<<<N_, 256>>>(pxe, pattself);
        si_kernel<<<NTOKS, 512>>>(pxe, pattself, pattint, att_fac, psi);

        sgemm(psi, WSIl, pxnew, NTOKS, D_, H_*D_, 0);

        sgemm(pxnew, ffs_w1 + (size_t)l*D_*DFF_, phidS, NTOKS, DFF_, D_, 1);
        sgemm(phidS, ffs_w2 + (size_t)l*DFF_*D_, ptmpS, NTOKS, D_, DFF_, 0);
        add_ln_kernel<<<NTOKS, 256>>>(ptmpS, pxnew, ffs_g + l*D_, ffs_b + l*D_, pxe);

        sgemm(pres,  ffi_w1 + (size_t)l*D_*DFF_, phidM, NTOKB, DFF_, D_, 1);
        sgemm(phidM, ffi_w2 + (size_t)l*DFF_*D_, ptmpM, NTOKB, D_, DFF_, 0);
        add_ln_kernel<<<NTOKB, 256>>>(ptmpM, pres, ffi_g + l*D_, ffi_b + l*D_, pne);
    }

    pred_kernel<<<(N_*T_*2+255)/256, 256>>>(pxe, Wpred, bpred, out);
}

// round 4
// speedup vs baseline: 2.4221x; 2.4221x over previous
#include <cuda_runtime.h>
#include <cuda_bf16.h>
#include <math.h>
#include <float.h>
#include <stdint.h>

// ---------------------------------------------------------------------------
// SocialTrans: T=16, N=64, NN=32, D=512, H=8, DK=64, DFF=2048, L=2
// GEMMs via mma.sync bf16 split-precision (AhBh+AhBl+AlBh, fp32 accum)
// ---------------------------------------------------------------------------
#define T_ 16
#define N_ 64
#define NN_ 32
#define D_ 512
#define H_ 8
#define DK_ 64
#define DFF_ 2048
#define L_ 2
#define NPAIR (N_*NN_)          // 2048
#define NTOKB (NPAIR*T_)        // 32768  neighbor tokens
#define NTOKS (N_*T_)           // 1024   self tokens

// ------------------------- device scratch (static, no allocs) --------------
__device__ float g_xf  [T_*N_*4];
__device__ float g_nf  [T_*N_*NN_*3];
__device__ unsigned char g_mask[NPAIR*T_];
__device__ float g_pe  [T_*D_];
__device__ float g_xe  [NTOKS*D_];
__device__ float g_ne  [NTOKB*D_];
__device__ float g_QKV [NTOKB*3*D_];
__device__ float g_ctx [NTOKB*D_];
__device__ float g_tmpM[NTOKB*D_];
__device__ float g_res [NTOKB*D_];
__device__ float g_hidM[NTOKB*DFF_];
__device__ float g_attn[NPAIR*H_*T_*T_];
__device__ float g_attint[N_*H_*T_*T_];
__device__ float g_attself[N_*T_*T_];
__device__ float g_si  [NTOKS*H_*D_];
__device__ float g_xnew[NTOKS*D_];
__device__ float g_hidS[NTOKS*DFF_];
__device__ float g_tmpS[NTOKS*D_];
__device__ __nv_bfloat16 g_Aq[134217728];   // max M*2K = 32768*4096
__device__ __nv_bfloat16 g_Bq[4194304];     // max 2K*N = 8192*512

// ------------------------- PTX helpers --------------------------------------
__device__ __forceinline__ uint32_t smem_u32(const void* p) {
    uint32_t a;
    asm("{ .reg .u64 t; cvta.to.shared.u64 t, %1; cvt.u32.u64 %0, t; }" : "=r"(a) : "l"(p));
    return a;
}
__device__ __forceinline__ void cp_async16(uint32_t saddr, const void* gaddr) {
    asm volatile("cp.async.cg.shared.global [%0], [%1], 16;" :: "r"(saddr), "l"(gaddr));
}
__device__ __forceinline__ void cp_commit() { asm volatile("cp.async.commit_group;" ::: "memory"); }
__device__ __forceinline__ void cp_wait1()  { asm volatile("cp.async.wait_group 1;" ::: "memory"); }

__device__ __forceinline__ void ldsm4(uint32_t* d, uint32_t a) {
    asm volatile("ldmatrix.sync.aligned.m8n8.x4.shared.b16 {%0,%1,%2,%3}, [%4];"
        : "=r"(d[0]), "=r"(d[1]), "=r"(d[2]), "=r"(d[3]) : "r"(a));
}
__device__ __forceinline__ void ldsm2t(uint32_t* d, uint32_t a) {
    asm volatile("ldmatrix.sync.aligned.m8n8.x2.trans.shared.b16 {%0,%1}, [%2];"
        : "=r"(d[0]), "=r"(d[1]) : "r"(a));
}
__device__ __forceinline__ void mma16816(float* d, const uint32_t* a, const uint32_t* b) {
    asm volatile("mma.sync.aligned.m16n8k16.row.col.f32.bf16.bf16.f32 "
        "{%0,%1,%2,%3}, {%4,%5,%6,%7}, {%8,%9}, {%0,%1,%2,%3};"
        : "+f"(d[0]), "+f"(d[1]), "+f"(d[2]), "+f"(d[3])
        : "r"(a[0]), "r"(a[1]), "r"(a[2]), "r"(a[3]), "r"(b[0]), "r"(b[1]));
}

// ------------------------- split conversion ----------------------------------
// Aq (M, 2K) = [Ah | Al], bf16, k-contiguous rows
__global__ void convA_kernel(const float* __restrict__ A, __nv_bfloat16* __restrict__ Aq,
                             int Khalf, int total) {   // total = M*K/2
    int idx = blockIdx.x * blockDim.x + threadIdx.x;
    if (idx >= total) return;
    int m = idx / Khalf, k2 = idx - m * Khalf;
    float2 v = ((const float2*)A)[idx];
    __nv_bfloat16 h0 = __float2bfloat16(v.x);
    __nv_bfloat16 h1 = __float2bfloat16(v.y);
    __nv_bfloat16 l0 = __float2bfloat16(v.x - __bfloat162float(h0));
    __nv_bfloat16 l1 = __float2bfloat16(v.y - __bfloat162float(h1));
    __nv_bfloat162* out = (__nv_bfloat162*)Aq;
    int K = Khalf * 2;
    out[(size_t)m*K + k2]         = __nv_bfloat162(h0, h1);
    out[(size_t)m*K + Khalf + k2] = __nv_bfloat162(l0, l1);
}
// Bq (2K, ldB) = [Bh ; Bl] from W (K, Nw) row-major; column offset via pointer.
__global__ void convB_kernel(const float* __restrict__ W, __nv_bfloat16* __restrict__ Bq,
                             int K, int Nw, int ldB) {
    int idx = blockIdx.x * blockDim.x + threadIdx.x;   // k*Nw + n
    if (idx >= K*Nw) return;
    int k = idx / Nw, n = idx - k*Nw;
    float a = W[idx];
    __nv_bfloat16 h = __float2bfloat16(a);
    __nv_bfloat16 l = __float2bfloat16(a - __bfloat162float(h));
    Bq[(size_t)k*ldB + n]       = h;
    Bq[(size_t)(K + k)*ldB + n] = l;
}

// ------------------------- mma.sync GEMM -------------------------------------
// C(M,N) = A(M,K) @ B(K,N): 3 passes AhBh + AhBl + AlBh.
// Aq (M,2K) m-major; Bq (2K,N) k-major.  M%128==0, N%128==0, K%32==0.
// 128x128x32 CTA tile, 8 warps (4 m x 2 n), warp tile 32x64, 3-stage cp.async.
__global__ void __launch_bounds__(256)
gemm3_kernel(const __nv_bfloat16* __restrict__ A, const __nv_bfloat16* __restrict__ B,
             float* __restrict__ C, int M, int N, int K, int relu) {
    __shared__ __align__(1024) char smem[3*16384];   // per stage: A 8KB + B 8KB
    int tid = threadIdx.x;
    int lane = tid & 31, wid = tid >> 5;
    int warp_m = wid & 3, warp_n = wid >> 2;
    int mBase = blockIdx.y * 128, nBase = blockIdx.x * 128;
    int ldA = 2*K, ldB = N;
    int KTp = K >> 5, KT = 3*KTp;
    uint32_t sbase = smem_u32(smem);

    // A smem: 128 rows x 64B (32 bf16), swizzle chunk c(0..3): c ^= (r>>1)&3
    // B smem: 32 k-rows x 256B (128 bf16), swizzle chunk c(0..15): c ^= r&7
    #define LOAD_STAGE(g, s) do { \
        int p_ = (g)/KTp, kt_ = (g) - p_*KTp; \
        int ka_ = ((p_==2)?K:0) + (kt_<<5); \
        int kb_ = ((p_==1)?K:0) + (kt_<<5); \
        uint32_t sa_ = sbase + (s)*16384; \
        uint32_t sb_ = sa_ + 8192; \
        const __nv_bfloat16* Ag_ = A + (size_t)mBase*ldA + ka_; \
        const __nv_bfloat16* Bg_ = B + (size_t)kb_*ldB + nBase; \
        _Pragma("unroll") \
        for (int i_ = 0; i_ < 2; i_++) { \
            int id_ = tid + i_*256; int r_ = id_ >> 2, c_ = id_ & 3; \
            cp_async16(sa_ + r_*64 + ((c_ ^ ((r_>>1)&3)) << 4), \
                       Ag_ + (size_t)r_*ldA + c_*8); \
        } \
        _Pragma("unroll") \
        for (int i_ = 0; i_ < 2; i_++) { \
            int id_ = tid + i_*256; int r_ = id_ >> 4, c_ = id_ & 15; \
            cp_async16(sb_ + r_*256 + ((c_ ^ (r_&7)) << 4), \
                       Bg_ + (size_t)r_*ldB + c_*8); \
        } \
    } while (0)

    LOAD_STAGE(0, 0); cp_commit();
    LOAD_STAGE(1, 1); cp_commit();

    float acc[2][8][4];
    #pragma unroll
    for (int mi = 0; mi < 2; mi++)
        #pragma unroll
        for (int ni = 0; ni < 8; ni++)
            #pragma unroll
            for (int j = 0; j < 4; j++) acc[mi][ni][j] = 0.0f;

    for (int g = 0; g < KT; g++) {
        cp_wait1();
        __syncthreads();
        uint32_t sa = sbase + (g % 3)*16384;
        uint32_t sb = sa + 8192;
        #pragma unroll
        for (int kh = 0; kh < 2; kh++) {
            uint32_t af[2][4];
            #pragma unroll
            for (int mi = 0; mi < 2; mi++) {
                int r = warp_m*32 + mi*16 + (lane & 15);
                int c = kh*2 + (lane >> 4);
                ldsm4(af[mi], sa + r*64 + ((c ^ ((r>>1)&3)) << 4));
            }
            uint32_t bfr[8][2];
            #pragma unroll
            for (int ni = 0; ni < 8; ni++) {
                int r = kh*16 + (lane & 15);
                int c = warp_n*8 + ni;
                ldsm2t(bfr[ni], sb + r*256 + ((c ^ (r&7)) << 4));
            }
            #pragma unroll
            for (int mi = 0; mi < 2; mi++)
                #pragma unroll
                for (int ni = 0; ni < 8; ni++)
                    mma16816(acc[mi][ni], af[mi], bfr[ni]);
        }
        if (g + 2 < KT) LOAD_STAGE(g + 2, (g + 2) % 3);
        cp_commit();
    }

    // epilogue
    #pragma unroll
    for (int mi = 0; mi < 2; mi++) {
        int r0 = mBase + warp_m*32 + mi*16 + (lane >> 2);
        #pragma unroll
        for (int ni = 0; ni < 8; ni++) {
            int col = nBase + warp_n*64 + ni*8 + (lane & 3)*2;
            float2 v0 = make_float2(acc[mi][ni][0], acc[mi][ni][1]);
            float2 v1 = make_float2(acc[mi][ni][2], acc[mi][ni][3]);
            if (relu) {
                v0.x = fmaxf(v0.x, 0.f); v0.y = fmaxf(v0.y, 0.f);
                v1.x = fmaxf(v1.x, 0.f); v1.y = fmaxf(v1.y, 0.f);
            }
            *(float2*)(C + (size_t)r0*N + col)     = v0;
            *(float2*)(C + (size_t)(r0+8)*N + col) = v1;
        }
    }
    #undef LOAD_STAGE
}

// ------------------------- helpers -----------------------------------------
__device__ __forceinline__ float n2n(float v) {
    if (isnan(v)) return 0.0f;
    if (isinf(v)) return v > 0.0f ? 3.4028235e38f : -3.4028235e38f;
    return v;
}

// ------------------------- feature kernel -----------------------------------
__global__ void feat_kernel(const float* __restrict__ x, const float* __restrict__ nb,
                            float* __restrict__ xf, float* __restrict__ nf,
                            unsigned char* __restrict__ mask) {
    int idx = blockIdx.x * blockDim.x + threadIdx.x;
    if (idx >= T_*N_*NN_) return;
    int nn = idx & (NN_-1);
    int rem = idx >> 5;
    int n  = rem & (N_-1);
    int t  = rem >> 6;
    const float* xr = x + ((size_t)t*N_ + n)*6;
    float px = xr[0], py = xr[1];
    float vx, vy;
    if (t == 0) {
        const float* x1 = x + ((size_t)1*N_ + n)*6;
        vx = x1[2]; vy = x1[3];
    } else {
        const float* xp = x + ((size_t)(t-1)*N_ + n)*6;
        vx = px - xp[0]; vy = py - xp[1];
    }
    const float* nr = nb + (((size_t)t*N_ + n)*NN_ + nn)*4;
    float dpx = nr[0]-px, dpy = nr[1]-py;
    float dvx = nr[2]-vx, dvy = nr[3]-vy;
    float dist = sqrtf(dpx*dpx + dpy*dpy);
    mask[(n*NN_ + nn)*T_ + t] = (dist <= 2.0f) ? 1 : 0;
    float nv = sqrtf(vx*vx + vy*vy);
    float bearing = (dpx*vx + dpy*vy) / (dist*nv);
    if (isnan(bearing)) bearing = 0.0f;
    float ndv = sqrtf(dvx*dvx + dvy*dvy);
    float tau = -(dpx*dvx + dpy*dvy) / ndv;
    if (isnan(tau)) tau = 0.0f;
    tau = fminf(fmaxf(tau, 0.0f), 7.0f);
    float mxx = dpx + tau*dvx, myy = dpy + tau*dvy;
    float mpd = sqrtf(mxx*mxx + myy*myy);
    float* o = nf + (size_t)idx*3;
    o[0] = n2n(dist); o[1] = n2n(bearing); o[2] = n2n(mpd);
    if (nn == 0) {
        float vel = sqrtf(xr[2]*xr[2] + xr[3]*xr[3]);
        float ang = atanf(xr[5]/xr[4]);
        float* xo = xf + ((size_t)t*N_ + n)*4;
        xo[0] = n2n(xr[0]); xo[1] = n2n(xr[1]); xo[2] = n2n(vel); xo[3] = n2n(ang);
    }
}

// ------------------------- positional encoding -------------------------------
__global__ void pe_kernel(float* __restrict__ pe) {
    int i = blockIdx.x * blockDim.x + threadIdx.x;
    if (i >= T_*D_) return;
    int t = i >> 9, d = i & (D_-1);
    double expo = (double)(d & ~1) / (double)D_;
    float div = (float)exp(expo * 9.210340371976184);
    float arg = (float)t * div;
    pe[i] = (d & 1) ? (float)cos((double)arg) : (float)sin((double)arg);
}

// ------------------------- embeddings ----------------------------------------
__global__ void xemb_kernel(const float* __restrict__ xf, const float* __restrict__ Wx,
                            const float* __restrict__ bx, const float* __restrict__ pe,
                            float* __restrict__ xe) {
    int i = blockIdx.x * blockDim.x + threadIdx.x;
    if (i >= NTOKS*D_) return;
    int d = i & (D_-1);
    int tok = i >> 9;
    int t = tok >> 6, n = tok & (N_-1);
    const float* f = xf + (size_t)tok*4;
    float acc = bx[d] + pe[t*D_ + d];
    #pragma unroll
    for (int k = 0; k < 4; k++) acc = fmaf(f[k], Wx[k*D_ + d], acc);
    xe[((size_t)(n*T_ + t))*D_ + d] = acc;
}

__global__ void nemb_kernel(const float* __restrict__ nf, const float* __restrict__ Wn,
                            const float* __restrict__ bn, const float* __restrict__ pe,
                            float* __restrict__ ne) {
    size_t i = (size_t)blockIdx.x * blockDim.x + threadIdx.x;
    if (i >= (size_t)NTOKB*D_) return;
    int d = (int)(i & (D_-1));
    int tok = (int)(i >> 9);
    int nn = tok & (NN_-1);
    int rem = tok >> 5;
    int n = rem & (N_-1);
    int t = rem >> 6;
    const float* f = nf + (size_t)tok*3;
    float acc = bn[d] + pe[t*D_ + d];
    acc = fmaf(f[0], Wn[d], acc);
    acc = fmaf(f[1], Wn[D_ + d], acc);
    acc = fmaf(f[2], Wn[2*D_ + d], acc);
    ne[(((size_t)(n*NN_ + nn))*T_ + t)*D_ + d] = acc;
}

// ------------------------- neighbor attention --------------------------------
// QKV fused buffer: row stride 1536, Q at +0, K at +512, V at +1024
__global__ void attn_kernel(const float* __restrict__ QKV, const unsigned char* __restrict__ mask,
                            float* __restrict__ ctx, float* __restrict__ attn_out) {
    int b = blockIdx.x;
    int h = b & (H_-1);
    int pair = b >> 3;
    int tid = threadIdx.x;
    __shared__ float q[16*68], k[16*68], v[16*68];
    __shared__ float at[16*17];
    size_t base = (size_t)pair*T_*1536 + h*DK_;
    for (int i = tid; i < 16*64; i += 256) {
        int t = i >> 6, d = i & 63;
        q[t*68+d] = QKV[base + (size_t)t*1536 + d];
        k[t*68+d] = QKV[base + (size_t)t*1536 + 512 + d];
        v[t*68+d] = QKV[base + (size_t)t*1536 + 1024 + d];
    }
    __syncthreads();
    int qt = tid >> 4, kt = tid & 15;
    float s = 0.0f;
    #pragma unroll
    for (int d = 0; d < 64; d++) s = fmaf(q[qt*68+d], k[kt*68+d], s);
    s *= 0.125f;
    if (!mask[pair*T_ + qt]) s = -1e9f;
    float mx = s;
    #pragma unroll
    for (int o = 8; o; o >>= 1) mx = fmaxf(mx, __shfl_xor_sync(0xffffffffu, mx, o));
    float e = expf(s - mx);
    float sum = e;
    #pragma unroll
    for (int o = 8; o; o >>= 1) sum += __shfl_xor_sync(0xffffffffu, sum, o);
    float a = e / sum;
    at[qt*17 + kt] = a;
    attn_out[(size_t)b*256 + qt*16 + kt] = a;
    __syncthreads();
    size_t cbase = (size_t)pair*T_*D_ + h*DK_;
    for (int i = tid; i < 16*64; i += 256) {
        int t = i >> 6, d = i & 63;
        float acc = 0.0f;
        #pragma unroll
        for (int kk = 0; kk < 16; kk++) acc = fmaf(at[t*17+kk], v[kk*68+d], acc);
        ctx[cbase + (size_t)t*D_ + d] = acc;
    }
}

__global__ void attmean_kernel(const float* __restrict__ attn, float* __restrict__ attint) {
    int i = blockIdx.x * blockDim.x + threadIdx.x;
    if (i >= N_*H_*256) return;
    int qk = i & 255;
    int h  = (i >> 8) & (H_-1);
    int n  = i >> 11;
    float s = 0.0f;
    #pragma unroll 4
    for (int nn = 0; nn < NN_; nn++)
        s += attn[(((size_t)(n*NN_ + nn)*H_ + h)*256) + qk];
    attint[i] = s * (1.0f/32.0f);
}

// ------------------------- add + layernorm -----------------------------------
__global__ void add_ln_kernel(const float* __restrict__ X, const float* __restrict__ R,
                              const float* __restrict__ g, const float* __restrict__ b,
                              float* __restrict__ out) {
    int row = blockIdx.x, tid = threadIdx.x;
    size_t off = (size_t)row*D_;
    float x0 = X[off+tid]     + R[off+tid];
    float x1 = X[off+256+tid] + R[off+256+tid];
    __shared__ float red[8], red2[8];
    float s = x0 + x1;
    #pragma unroll
    for (int o = 16; o; o >>= 1) s += __shfl_xor_sync(0xffffffffu, s, o);
    if ((tid & 31) == 0) red[tid >> 5] = s;
    __syncthreads();
    float tot = 0.0f;
    #pragma unroll
    for (int i = 0; i < 8; i++) tot += red[i];
    float m = tot * (1.0f/512.0f);
    float d0 = x0 - m, d1 = x1 - m;
    float vs = d0*d0 + d1*d1;
    #pragma unroll
    for (int o = 16; o; o >>= 1) vs += __shfl_xor_sync(0xffffffffu, vs, o);
    if ((tid & 31) == 0) red2[tid >> 5] = vs;
    __syncthreads();
    float vtot = 0.0f;
    #pragma unroll
    for (int i = 0; i < 8; i++) vtot += red2[i];
    float inv = 1.0f / sqrtf(vtot * (1.0f/512.0f) + 1e-5f);
    out[off+tid]     = d0*inv*g[tid]     + b[tid];
    out[off+256+tid] = d1*inv*g[tid+256] + b[tid+256];
}

// ------------------------- self attention ------------------------------------
__global__ void attself_kernel(const float* __restrict__ xe, float* __restrict__ attself) {
    int n = blockIdx.x;
    int tid = threadIdx.x;
    __shared__ float xs[16*516];
    for (int i = tid; i < 16*D_; i += 256) {
        int t = i >> 9, d = i & (D_-1);
        xs[t*516 + d] = xe[((size_t)(n*T_ + t))*D_ + d];
    }
    __syncthreads();
    int q = tid >> 4, k = tid & 15;
    float s = 0.0f;
    for (int d = 0; d < D_; d++) s = fmaf(xs[q*516+d], xs[k*516+d], s);
    s *= 0.04419417382415922f;
    float mx = s;
    #pragma unroll
    for (int o = 8; o; o >>= 1) mx = fmaxf(mx, __shfl_xor_sync(0xffffffffu, mx, o));
    float e = expf(s - mx);
    float sum = e;
    #pragma unroll
    for (int o = 8; o; o >>= 1) sum += __shfl_xor_sync(0xffffffffu, sum, o);
    attself[(size_t)n*256 + q*16 + k] = e / sum;
}

// ------------------------- si = (att_self + f*att_inter) @ x_emb -------------
__global__ void si_kernel(const float* __restrict__ xe, const float* __restrict__ attself,
                          const float* __restrict__ attint, const float* __restrict__ att_factor,
                          float* __restrict__ si) {
    int n = blockIdx.x >> 4;
    int q = blockIdx.x & 15;
    int tid = threadIdx.x;
    __shared__ float xs[16*512];
    __shared__ float arow[H_*16];
    float factor = att_factor[0];
    for (int i = tid; i < 16*D_; i += 512) xs[i] = xe[(size_t)n*T_*D_ + i];
    if (tid < H_*16) {
        int h = tid >> 4, t = tid & 15;
        arow[tid] = attself[(size_t)n*256 + q*16 + t]
                  + factor * attint[((n*H_ + h)*16 + q)*16 + t];
    }
    __syncthreads();
    int d = tid;
    #pragma unroll
    for (int h = 0; h < H_; h++) {
        float acc = 0.0f;
        #pragma unroll
        for (int t = 0; t < 16; t++) acc = fmaf(arow[h*16+t], xs[t*512 + d], acc);
        si[((size_t)(n*T_ + q))*(H_*D_) + h*D_ + d] = acc;
    }
}

// ------------------------- prediction head -----------------------------------
__global__ void pred_kernel(const float* __restrict__ xe, const float* __restrict__ Wp,
                            const float* __restrict__ bp, float* __restrict__ out) {
    int idx = blockIdx.x * blockDim.x + threadIdx.x;
    if (idx >= N_*T_*2) return;
    int c = idx & 1;
    int t = (idx >> 1) & 15;
    int n = idx >> 5;
    float acc = bp[c];
    const float* xr = xe + ((size_t)(n*T_ + t))*D_;
    for (int d = 0; d < D_; d++) acc = fmaf(xr[d], Wp[d*2 + c], acc);
    for (int p = 0; p < 20; p++)
        out[(((size_t)p*T_ + t)*N_ + n)*2 + c] = acc;
}

// ---------------------------------------------------------------------------
static inline void convA(const float* A, __nv_bfloat16* Aq, int M, int K) {
    int total = M*(K/2);
    convA_kernel<<<(total+255)/256, 256>>>(A, Aq, K/2, total);
}
static inline void convB(const float* W, __nv_bfloat16* Bq, int K, int Nw, int ldB) {
    convB_kernel<<<(K*Nw+255)/256, 256>>>(W, Bq, K, Nw, ldB);
}
static inline void gemm3(const __nv_bfloat16* Aq, const __nv_bfloat16* Bq, float* C,
                         int M, int N, int K, int relu) {
    dim3 grid(N/128, M/128);
    gemm3_kernel<<<grid, 256>>>(Aq, Bq, C, M, N, K, relu);
}

extern "C" void kernel_launch(void* const* d_in, const int* in_sizes, int n_in,
                              void* d_out, int out_size) {
    const float* x        = (const float*)d_in[0];
    const float* neighbor = (const float*)d_in[1];
    const float* att_fac  = (const float*)d_in[2];
    const float* Wx       = (const float*)d_in[3];
    const float* bx       = (const float*)d_in[4];
    const float* Wn       = (const float*)d_in[5];
    const float* bn       = (const float*)d_in[6];
    const float* Wpred    = (const float*)d_in[7];
    const float* bpred    = (const float*)d_in[8];
    const float* WQ       = (const float*)d_in[9];
    const float* WK       = (const float*)d_in[10];
    const float* WV       = (const float*)d_in[11];
    const float* Wfc      = (const float*)d_in[12];
    const float* mha_g    = (const float*)d_in[13];
    const float* mha_b    = (const float*)d_in[14];
    const float* WSI      = (const float*)d_in[15];
    const float* ffs_w1   = (const float*)d_in[16];
    const float* ffs_w2   = (const float*)d_in[17];
    const float* ffs_g    = (const float*)d_in[18];
    const float* ffs_b    = (const float*)d_in[19];
    const float* ffi_w1   = (const float*)d_in[20];
    const float* ffi_w2   = (const float*)d_in[21];
    const float* ffi_g    = (const float*)d_in[22];
    const float* ffi_b    = (const float*)d_in[23];
    float* out = (float*)d_out;

    static float *pxf=0,*pnf=0,*ppe=0,*pxe=0,*pne=0,*pqkv=0,*pctx=0,
                 *ptmpM=0,*pres=0,*phidM=0,*pattn=0,*pattint=0,*pattself=0,
                 *psi=0,*pxnew=0,*phidS=0,*ptmpS=0;
    static __nv_bfloat16 *pAq=0, *pBq=0;
    static unsigned char* pmask=0;
    if (!pxf) {
        cudaGetSymbolAddress((void**)&pxf, g_xf);
        cudaGetSymbolAddress((void**)&pnf, g_nf);
        cudaGetSymbolAddress((void**)&pmask, g_mask);
        cudaGetSymbolAddress((void**)&ppe, g_pe);
        cudaGetSymbolAddress((void**)&pxe, g_xe);
        cudaGetSymbolAddress((void**)&pne, g_ne);
        cudaGetSymbolAddress((void**)&pqkv, g_QKV);
        cudaGetSymbolAddress((void**)&pctx, g_ctx);
        cudaGetSymbolAddress((void**)&ptmpM, g_tmpM);
        cudaGetSymbolAddress((void**)&pres, g_res);
        cudaGetSymbolAddress((void**)&phidM, g_hidM);
        cudaGetSymbolAddress((void**)&pattn, g_attn);
        cudaGetSymbolAddress((void**)&pattint, g_attint);
        cudaGetSymbolAddress((void**)&pattself, g_attself);
        cudaGetSymbolAddress((void**)&psi, g_si);
        cudaGetSymbolAddress((void**)&pxnew, g_xnew);
        cudaGetSymbolAddress((void**)&phidS, g_hidS);
        cudaGetSymbolAddress((void**)&ptmpS, g_tmpS);
        cudaGetSymbolAddress((void**)&pAq, g_Aq);
        cudaGetSymbolAddress((void**)&pBq, g_Bq);
    }

    feat_kernel<<<(T_*N_*NN_+255)/256, 256>>>(x, neighbor, pxf, pnf, pmask);
    pe_kernel<<<(T_*D_+255)/256, 256>>>(ppe);
    xemb_kernel<<<(NTOKS*D_+255)/256, 256>>>(pxf, Wx, bx, ppe, pxe);
    nemb_kernel<<<(int)(((size_t)NTOKB*D_+255)/256), 256>>>(pnf, Wn, bn, ppe, pne);

    for (int l = 0; l < L_; l++) {
        const float* WQl  = WQ  + (size_t)l*D_*D_;
        const float* WKl  = WK  + (size_t)l*D_*D_;
        const float* WVl  = WV  + (size_t)l*D_*D_;
        const float* Wfcl = Wfc + (size_t)l*D_*D_;
        const float* WSIl = WSI + (size_t)l*(H_*D_)*D_;

        // fused QKV: Bq (2*512, 1536) with col blocks Q|K|V
        convA(pne, pAq, NTOKB, D_);
        convB(WQl, pBq,        D_, D_, 1536);
        convB(WKl, pBq + 512,  D_, D_, 1536);
        convB(WVl, pBq + 1024, D_, D_, 1536);
        gemm3(pAq, pBq, pqkv, NTOKB, 3*D_, D_, 0);

        attn_kernel<<<NPAIR*H_, 256>>>(pqkv, pmask, pctx, pattn);
        attmean_kernel<<<(N_*H_*256+255)/256, 256>>>(pattn, pattint);

        convA(pctx, pAq, NTOKB, D_);
        convB(Wfcl, pBq, D_, D_, D_);
        gemm3(pAq, pBq, ptmpM, NTOKB, D_, D_, 0);
        add_ln_kernel<<<NTOKB, 256>>>(ptmpM, pne, mha_g + l*D_, mha_b + l*D_, pres);

        attself_kernel<<<N_, 256>>>(pxe, pattself);
        si_kernel<<<NTOKS, 512>>>(pxe, pattself, pattint, att_fac, psi);

        convA(psi, pAq, NTOKS, H_*D_);
        convB(WSIl, pBq, H_*D_, D_, D_);
        gemm3(pAq, pBq, pxnew, NTOKS, D_, H_*D_, 0);

        convA(pxnew, pAq, NTOKS, D_);
        convB(ffs_w1 + (size_t)l*D_*DFF_, pBq, D_, DFF_, DFF_);
        gemm3(pAq, pBq, phidS, NTOKS, DFF_, D_, 1);
        convA(phidS, pAq, NTOKS, DFF_);
        convB(ffs_w2 + (size_t)l*DFF_*D_, pBq, DFF_, D_, D_);
        gemm3(pAq, pBq, ptmpS, NTOKS, D_, DFF_, 0);
        add_ln_kernel<<<NTOKS, 256>>>(ptmpS, pxnew, ffs_g + l*D_, ffs_b + l*D_, pxe);

        convA(pres, pAq, NTOKB, D_);
        convB(ffi_w1 + (size_t)l*D_*DFF_, pBq, D_, DFF_, DFF_);
        gemm3(pAq, pBq, phidM, NTOKB, DFF_, D_, 1);
        convA(phidM, pAq, NTOKB, DFF_);
        convB(ffi_w2 + (size_t)l*DFF_*D_, pBq, DFF_, D_, D_);
        gemm3(pAq, pBq, ptmpM, NTOKB, D_, DFF_, 0);
        add_ln_kernel<<<NTOKB, 256>>>(ptmpM, pres, ffi_g + l*D_, ffi_b + l*D_, pne);
    }

    pred_kernel<<<(N_*T_*2+255)/256, 256>>>(pxe, Wpred, bpred, out);
}

// round 9
// speedup vs baseline: 2.5092x; 1.0360x over previous
#include <cuda_runtime.h>
#include <cuda_bf16.h>
#include <math.h>
#include <float.h>
#include <stdint.h>

// ---------------------------------------------------------------------------
// SocialTrans: T=16, N=64, NN=32, D=512, H=8, DK=64, DFF=2048, L=2
// GEMMs via mma.sync bf16 split-precision (AhBh+AhBl+AlBh, fp32 accum).
// Split conversion fused into all producers (no standalone convA passes).
// ---------------------------------------------------------------------------
#define T_ 16
#define N_ 64
#define NN_ 32
#define D_ 512
#define H_ 8
#define DK_ 64
#define DFF_ 2048
#define L_ 2
#define NPAIR (N_*NN_)          // 2048
#define NTOKB (NPAIR*T_)        // 32768  neighbor tokens
#define NTOKS (N_*T_)           // 1024   self tokens

#define GF_RELU 1
#define GF_SPLIT 2
#define GF_F32 4

// ------------------------- device scratch (static, no allocs) --------------
__device__ float g_xf  [T_*N_*4];
__device__ float g_nf  [T_*N_*NN_*3];
__device__ unsigned char g_mask[NPAIR*T_];
__device__ float g_pe  [T_*D_];
__device__ float g_xe  [NTOKS*D_];
__device__ float g_ne  [NTOKB*D_];
__device__ float g_QKV [NTOKB*3*D_];
__device__ float g_tmpM[NTOKB*D_];
__device__ float g_res [NTOKB*D_];
__device__ float g_attn[NPAIR*H_*T_*T_];
__device__ float g_attint[N_*H_*T_*T_];
__device__ float g_attself[N_*T_*T_];
__device__ float g_xnew[NTOKS*D_];
__device__ float g_tmpS[NTOKS*D_];
// split (hi|lo) bf16 buffers, row stride = 2K
__device__ __nv_bfloat16 g_spNe  [NTOKB*2*D_];
__device__ __nv_bfloat16 g_spCtx [NTOKB*2*D_];
__device__ __nv_bfloat16 g_spRes [NTOKB*2*D_];
__device__ __nv_bfloat16 g_spHidM[(size_t)NTOKB*2*DFF_];
__device__ __nv_bfloat16 g_spSi  [NTOKS*2*H_*D_];
__device__ __nv_bfloat16 g_spXnew[NTOKS*2*D_];
__device__ __nv_bfloat16 g_spHidS[NTOKS*2*DFF_];
__device__ __nv_bfloat16 g_Bq[4194304];     // weights: max 2K*N = 8192*512 (QKV: 1024*1536)

// ------------------------- PTX helpers --------------------------------------
__device__ __forceinline__ uint32_t smem_u32(const void* p) {
    uint32_t a;
    asm("{ .reg .u64 t; cvta.to.shared.u64 t, %1; cvt.u32.u64 %0, t; }" : "=r"(a) : "l"(p));
    return a;
}
__device__ __forceinline__ void cp_async16(uint32_t saddr, const void* gaddr) {
    asm volatile("cp.async.cg.shared.global [%0], [%1], 16;" :: "r"(saddr), "l"(gaddr));
}
__device__ __forceinline__ void cp_commit() { asm volatile("cp.async.commit_group;" ::: "memory"); }
__device__ __forceinline__ void cp_wait1()  { asm volatile("cp.async.wait_group 1;" ::: "memory"); }

__device__ __forceinline__ void ldsm4(uint32_t* d, uint32_t a) {
    asm volatile("ldmatrix.sync.aligned.m8n8.x4.shared.b16 {%0,%1,%2,%3}, [%4];"
        : "=r"(d[0]), "=r"(d[1]), "=r"(d[2]), "=r"(d[3]) : "r"(a));
}
__device__ __forceinline__ void ldsm2t(uint32_t* d, uint32_t a) {
    asm volatile("ldmatrix.sync.aligned.m8n8.x2.trans.shared.b16 {%0,%1}, [%2];"
        : "=r"(d[0]), "=r"(d[1]) : "r"(a));
}
__device__ __forceinline__ void mma16816(float* d, const uint32_t* a, const uint32_t* b) {
    asm volatile("mma.sync.aligned.m16n8k16.row.col.f32.bf16.bf16.f32 "
        "{%0,%1,%2,%3}, {%4,%5,%6,%7}, {%8,%9}, {%0,%1,%2,%3};"
        : "+f"(d[0]), "+f"(d[1]), "+f"(d[2]), "+f"(d[3])
        : "r"(a[0]), "r"(a[1]), "r"(a[2]), "r"(a[3]), "r"(b[0]), "r"(b[1]));
}
__device__ __forceinline__ void split2(float x, float y, __nv_bfloat162& hi, __nv_bfloat162& lo) {
    __nv_bfloat16 hx = __float2bfloat16(x);
    __nv_bfloat16 hy = __float2bfloat16(y);
    hi = __nv_bfloat162(hx, hy);
    lo = __nv_bfloat162(__float2bfloat16(x - __bfloat162float(hx)),
                        __float2bfloat16(y - __bfloat162float(hy)));
}

// ------------------------- weight conversion ---------------------------------
// Bq (2K, ldB) = [Bh ; Bl] from W (K, Nw) row-major; column offset via pointer.
__global__ void convB_kernel(const float* __restrict__ W, __nv_bfloat16* __restrict__ Bq,
                             int K, int Nw, int ldB) {
    int idx = blockIdx.x * blockDim.x + threadIdx.x;   // k*Nw + n
    if (idx >= K*Nw) return;
    int k = idx / Nw, n = idx - k*Nw;
    float a = W[idx];
    __nv_bfloat16 h = __float2bfloat16(a);
    __nv_bfloat16 l = __float2bfloat16(a - __bfloat162float(h));
    Bq[(size_t)k*ldB + n]       = h;
    Bq[(size_t)(K + k)*ldB + n] = l;
}

// ------------------------- mma.sync GEMM -------------------------------------
// C(M,N) = A(M,K) @ B(K,N): 3 passes AhBh + AhBl + AlBh.
// A (M,2K) m-major split; B (2K,N) k-major split.  M%128==0, N%128==0, K%32==0.
// Outputs: GF_F32 -> C fp32 (ld N); GF_SPLIT -> Csp (M,2N) split bf16.
__global__ void __launch_bounds__(256)
gemm3_kernel(const __nv_bfloat16* __restrict__ A, const __nv_bfloat16* __restrict__ B,
             float* __restrict__ C, __nv_bfloat16* __restrict__ Csp,
             int M, int N, int K, int flags) {
    __shared__ __align__(1024) char smem[3*16384];   // per stage: A 8KB + B 8KB
    int tid = threadIdx.x;
    int lane = tid & 31, wid = tid >> 5;
    int warp_m = wid & 3, warp_n = wid >> 2;
    int mBase = blockIdx.y * 128, nBase = blockIdx.x * 128;
    int ldA = 2*K, ldB = N;
    int KTp = K >> 5, KT = 3*KTp;
    uint32_t sbase = smem_u32(smem);

    #define LOAD_STAGE(g, s) do { \
        int p_ = (g)/KTp, kt_ = (g) - p_*KTp; \
        int ka_ = ((p_==2)?K:0) + (kt_<<5); \
        int kb_ = ((p_==1)?K:0) + (kt_<<5); \
        uint32_t sa_ = sbase + (s)*16384; \
        uint32_t sb_ = sa_ + 8192; \
        const __nv_bfloat16* Ag_ = A + (size_t)mBase*ldA + ka_; \
        const __nv_bfloat16* Bg_ = B + (size_t)kb_*ldB + nBase; \
        _Pragma("unroll") \
        for (int i_ = 0; i_ < 2; i_++) { \
            int id_ = tid + i_*256; int r_ = id_ >> 2, c_ = id_ & 3; \
            cp_async16(sa_ + r_*64 + ((c_ ^ ((r_>>1)&3)) << 4), \
                       Ag_ + (size_t)r_*ldA + c_*8); \
        } \
        _Pragma("unroll") \
        for (int i_ = 0; i_ < 2; i_++) { \
            int id_ = tid + i_*256; int r_ = id_ >> 4, c_ = id_ & 15; \
            cp_async16(sb_ + r_*256 + ((c_ ^ (r_&7)) << 4), \
                       Bg_ + (size_t)r_*ldB + c_*8); \
        } \
    } while (0)

    LOAD_STAGE(0, 0); cp_commit();
    LOAD_STAGE(1, 1); cp_commit();

    float acc[2][8][4];
    #pragma unroll
    for (int mi = 0; mi < 2; mi++)
        #pragma unroll
        for (int ni = 0; ni < 8; ni++)
            #pragma unroll
            for (int j = 0; j < 4; j++) acc[mi][ni][j] = 0.0f;

    for (int g = 0; g < KT; g++) {
        cp_wait1();
        __syncthreads();
        uint32_t sa = sbase + (g % 3)*16384;
        uint32_t sb = sa + 8192;
        #pragma unroll
        for (int kh = 0; kh < 2; kh++) {
            uint32_t af[2][4];
            #pragma unroll
            for (int mi = 0; mi < 2; mi++) {
                int r = warp_m*32 + mi*16 + (lane & 15);
                int c = kh*2 + (lane >> 4);
                ldsm4(af[mi], sa + r*64 + ((c ^ ((r>>1)&3)) << 4));
            }
            uint32_t bfr[8][2];
            #pragma unroll
            for (int ni = 0; ni < 8; ni++) {
                int r = kh*16 + (lane & 15);
                int c = warp_n*8 + ni;
                ldsm2t(bfr[ni], sb + r*256 + ((c ^ (r&7)) << 4));
            }
            #pragma unroll
            for (int mi = 0; mi < 2; mi++)
                #pragma unroll
                for (int ni = 0; ni < 8; ni++)
                    mma16816(acc[mi][ni], af[mi], bfr[ni]);
        }
        if (g + 2 < KT) LOAD_STAGE(g + 2, (g + 2) % 3);
        cp_commit();
    }

    // epilogue
    int relu = flags & GF_RELU;
    #pragma unroll
    for (int mi = 0; mi < 2; mi++) {
        int r0 = mBase + warp_m*32 + mi*16 + (lane >> 2);
        #pragma unroll
        for (int ni = 0; ni < 8; ni++) {
            int col = nBase + warp_n*64 + ni*8 + (lane & 3)*2;
            float2 v0 = make_float2(acc[mi][ni][0], acc[mi][ni][1]);
            float2 v1 = make_float2(acc[mi][ni][2], acc[mi][ni][3]);
            if (relu) {
                v0.x = fmaxf(v0.x, 0.f); v0.y = fmaxf(v0.y, 0.f);
                v1.x = fmaxf(v1.x, 0.f); v1.y = fmaxf(v1.y, 0.f);
            }
            if (flags & GF_F32) {
                *(float2*)(C + (size_t)r0*N + col)     = v0;
                *(float2*)(C + (size_t)(r0+8)*N + col) = v1;
            }
            if (flags & GF_SPLIT) {
                __nv_bfloat162 hi, lo;
                split2(v0.x, v0.y, hi, lo);
                *(__nv_bfloat162*)(Csp + (size_t)r0*2*N + col)     = hi;
                *(__nv_bfloat162*)(Csp + (size_t)r0*2*N + N + col) = lo;
                split2(v1.x, v1.y, hi, lo);
                *(__nv_bfloat162*)(Csp + (size_t)(r0+8)*2*N + col)     = hi;
                *(__nv_bfloat162*)(Csp + (size_t)(r0+8)*2*N + N + col) = lo;
            }
        }
    }
    #undef LOAD_STAGE
}

// ------------------------- helpers -----------------------------------------
__device__ __forceinline__ float n2n(float v) {
    if (isnan(v)) return 0.0f;
    if (isinf(v)) return v > 0.0f ? 3.4028235e38f : -3.4028235e38f;
    return v;
}
__device__ __forceinline__ void splitw(__nv_bfloat16* sp, size_t hi_idx, size_t lo_idx, float v) {
    __nv_bfloat16 h = __float2bfloat16(v);
    sp[hi_idx] = h;
    sp[lo_idx] = __float2bfloat16(v - __bfloat162float(h));
}

// ------------------------- feature kernel -----------------------------------
__global__ void feat_kernel(const float* __restrict__ x, const float* __restrict__ nb,
                            float* __restrict__ xf, float* __restrict__ nf,
                            unsigned char* __restrict__ mask) {
    int idx = blockIdx.x * blockDim.x + threadIdx.x;
    if (idx >= T_*N_*NN_) return;
    int nn = idx & (NN_-1);
    int rem = idx >> 5;
    int n  = rem & (N_-1);
    int t  = rem >> 6;
    const float* xr = x + ((size_t)t*N_ + n)*6;
    float px = xr[0], py = xr[1];
    float vx, vy;
    if (t == 0) {
        const float* x1 = x + ((size_t)1*N_ + n)*6;
        vx = x1[2]; vy = x1[3];
    } else {
        const float* xp = x + ((size_t)(t-1)*N_ + n)*6;
        vx = px - xp[0]; vy = py - xp[1];
    }
    const float* nr = nb + (((size_t)t*N_ + n)*NN_ + nn)*4;
    float dpx = nr[0]-px, dpy = nr[1]-py;
    float dvx = nr[2]-vx, dvy = nr[3]-vy;
    float dist = sqrtf(dpx*dpx + dpy*dpy);
    mask[(n*NN_ + nn)*T_ + t] = (dist <= 2.0f) ? 1 : 0;
    float nv = sqrtf(vx*vx + vy*vy);
    float bearing = (dpx*vx + dpy*vy) / (dist*nv);
    if (isnan(bearing)) bearing = 0.0f;
    float ndv = sqrtf(dvx*dvx + dvy*dvy);
    float tau = -(dpx*dvx + dpy*dvy) / ndv;
    if (isnan(tau)) tau = 0.0f;
    tau = fminf(fmaxf(tau, 0.0f), 7.0f);
    float mxx = dpx + tau*dvx, myy = dpy + tau*dvy;
    float mpd = sqrtf(mxx*mxx + myy*myy);
    float* o = nf + (size_t)idx*3;
    o[0] = n2n(dist); o[1] = n2n(bearing); o[2] = n2n(mpd);
    if (nn == 0) {
        float vel = sqrtf(xr[2]*xr[2] + xr[3]*xr[3]);
        float ang = atanf(xr[5]/xr[4]);
        float* xo = xf + ((size_t)t*N_ + n)*4;
        xo[0] = n2n(xr[0]); xo[1] = n2n(xr[1]); xo[2] = n2n(vel); xo[3] = n2n(ang);
    }
}

// ------------------------- positional encoding -------------------------------
__global__ void pe_kernel(float* __restrict__ pe) {
    int i = blockIdx.x * blockDim.x + threadIdx.x;
    if (i >= T_*D_) return;
    int t = i >> 9, d = i & (D_-1);
    double expo = (double)(d & ~1) / (double)D_;
    float div = (float)exp(expo * 9.210340371976184);
    float arg = (float)t * div;
    pe[i] = (d & 1) ? (float)cos((double)arg) : (float)sin((double)arg);
}

// ------------------------- embeddings ----------------------------------------
__global__ void xemb_kernel(const float* __restrict__ xf, const float* __restrict__ Wx,
                            const float* __restrict__ bx, const float* __restrict__ pe,
                            float* __restrict__ xe) {
    int i = blockIdx.x * blockDim.x + threadIdx.x;
    if (i >= NTOKS*D_) return;
    int d = i & (D_-1);
    int tok = i >> 9;
    int t = tok >> 6, n = tok & (N_-1);
    const float* f = xf + (size_t)tok*4;
    float acc = bx[d] + pe[t*D_ + d];
    #pragma unroll
    for (int k = 0; k < 4; k++) acc = fmaf(f[k], Wx[k*D_ + d], acc);
    xe[((size_t)(n*T_ + t))*D_ + d] = acc;
}

// writes ne fp32 (residual use) + split bf16 (GEMM A use)
__global__ void nemb_kernel(const float* __restrict__ nf, const float* __restrict__ Wn,
                            const float* __restrict__ bn, const float* __restrict__ pe,
                            float* __restrict__ ne, __nv_bfloat16* __restrict__ sp) {
    size_t i = (size_t)blockIdx.x * blockDim.x + threadIdx.x;
    if (i >= (size_t)NTOKB*D_) return;
    int d = (int)(i & (D_-1));
    int tok = (int)(i >> 9);
    int nn = tok & (NN_-1);
    int rem = tok >> 5;
    int n = rem & (N_-1);
    int t = rem >> 6;
    const float* f = nf + (size_t)tok*3;
    float acc = bn[d] + pe[t*D_ + d];
    acc = fmaf(f[0], Wn[d], acc);
    acc = fmaf(f[1], Wn[D_ + d], acc);
    acc = fmaf(f[2], Wn[2*D_ + d], acc);
    size_t row = (size_t)(n*NN_ + nn)*T_ + t;
    ne[row*D_ + d] = acc;
    splitw(sp, row*2*D_ + d, row*2*D_ + D_ + d, acc);
}

// ------------------------- neighbor attention --------------------------------
// QKV fused buffer: row stride 1536, Q at +0, K at +512, V at +1024
// ctx written directly as split bf16 (row stride 1024)
__global__ void attn_kernel(const float* __restrict__ QKV, const unsigned char* __restrict__ mask,
                            __nv_bfloat16* __restrict__ spCtx, float* __restrict__ attn_out) {
    int b = blockIdx.x;
    int h = b & (H_-1);
    int pair = b >> 3;
    int tid = threadIdx.x;
    __shared__ float q[16*68], k[16*68], v[16*68];
    __shared__ float at[16*17];
    size_t base = (size_t)pair*T_*1536 + h*DK_;
    for (int i = tid; i < 16*64; i += 256) {
        int t = i >> 6, d = i & 63;
        q[t*68+d] = QKV[base + (size_t)t*1536 + d];
        k[t*68+d] = QKV[base + (size_t)t*1536 + 512 + d];
        v[t*68+d] = QKV[base + (size_t)t*1536 + 1024 + d];
    }
    __syncthreads();
    int qt = tid >> 4, kt = tid & 15;
    float s = 0.0f;
    #pragma unroll
    for (int d = 0; d < 64; d++) s = fmaf(q[qt*68+d], k[kt*68+d], s);
    s *= 0.125f;
    if (!mask[pair*T_ + qt]) s = -1e9f;
    float mx = s;
    #pragma unroll
    for (int o = 8; o; o >>= 1) mx = fmaxf(mx, __shfl_xor_sync(0xffffffffu, mx, o));
    float e = expf(s - mx);
    float sum = e;
    #pragma unroll
    for (int o = 8; o; o >>= 1) sum += __shfl_xor_sync(0xffffffffu, sum, o);
    float a = e / sum;
    at[qt*17 + kt] = a;
    attn_out[(size_t)b*256 + qt*16 + kt] = a;
    __syncthreads();
    for (int i = tid; i < 16*64; i += 256) {
        int t = i >> 6, d = i & 63;
        float acc = 0.0f;
        #pragma unroll
        for (int kk = 0; kk < 16; kk++) acc = fmaf(at[t*17+kk], v[kk*68+d], acc);
        size_t row = (size_t)pair*T_ + t;
        splitw(spCtx, row*1024 + h*DK_ + d, row*1024 + 512 + h*DK_ + d, acc);
    }
}

__global__ void attmean_kernel(const float* __restrict__ attn, float* __restrict__ attint) {
    int i = blockIdx.x * blockDim.x + threadIdx.x;
    if (i >= N_*H_*256) return;
    int qk = i & 255;
    int h  = (i >> 8) & (H_-1);
    int n  = i >> 11;
    float s = 0.0f;
    #pragma unroll 4
    for (int nn = 0; nn < NN_; nn++)
        s += attn[(((size_t)(n*NN_ + nn)*H_ + h)*256) + qk];
    attint[i] = s * (1.0f/32.0f);
}

// ------------------------- add + layernorm (optional split out) --------------
__global__ void add_ln_kernel(const float* __restrict__ X, const float* __restrict__ R,
                              const float* __restrict__ g, const float* __restrict__ b,
                              float* __restrict__ out, __nv_bfloat16* __restrict__ sp) {
    int row = blockIdx.x, tid = threadIdx.x;
    size_t off = (size_t)row*D_;
    float x0 = X[off+tid]     + R[off+tid];
    float x1 = X[off+256+tid] + R[off+256+tid];
    __shared__ float red[8], red2[8];
    float s = x0 + x1;
    #pragma unroll
    for (int o = 16; o; o >>= 1) s += __shfl_xor_sync(0xffffffffu, s, o);
    if ((tid & 31) == 0) red[tid >> 5] = s;
    __syncthreads();
    float tot = 0.0f;
    #pragma unroll
    for (int i = 0; i < 8; i++) tot += red[i];
    float m = tot * (1.0f/512.0f);
    float d0 = x0 - m, d1 = x1 - m;
    float vs = d0*d0 + d1*d1;
    #pragma unroll
    for (int o = 16; o; o >>= 1) vs += __shfl_xor_sync(0xffffffffu, vs, o);
    if ((tid & 31) == 0) red2[tid >> 5] = vs;
    __syncthreads();
    float vtot = 0.0f;
    #pragma unroll
    for (int i = 0; i < 8; i++) vtot += red2[i];
    float inv = 1.0f / sqrtf(vtot * (1.0f/512.0f) + 1e-5f);
    float o0 = d0*inv*g[tid]     + b[tid];
    float o1 = d1*inv*g[tid+256] + b[tid+256];
    out[off+tid]     = o0;
    out[off+256+tid] = o1;
    if (sp) {
        size_t sro = (size_t)row*1024;
        splitw(sp, sro + tid,       sro + 512 + tid,       o0);
        splitw(sp, sro + 256 + tid, sro + 768 + tid,       o1);
    }
}

// ------------------------- self attention ------------------------------------
__global__ void attself_kernel(const float* __restrict__ xe, float* __restrict__ attself) {
    int n = blockIdx.x;
    int tid = threadIdx.x;
    __shared__ float xs[16*516];
    for (int i = tid; i < 16*D_; i += 256) {
        int t = i >> 9, d = i & (D_-1);
        xs[t*516 + d] = xe[((size_t)(n*T_ + t))*D_ + d];
    }
    __syncthreads();
    int q = tid >> 4, k = tid & 15;
    float s = 0.0f;
    for (int d = 0; d < D_; d++) s = fmaf(xs[q*516+d], xs[k*516+d], s);
    s *= 0.04419417382415922f;
    float mx = s;
    #pragma unroll
    for (int o = 8; o; o >>= 1) mx = fmaxf(mx, __shfl_xor_sync(0xffffffffu, mx, o));
    float e = expf(s - mx);
    float sum = e;
    #pragma unroll
    for (int o = 8; o; o >>= 1) sum += __shfl_xor_sync(0xffffffffu, sum, o);
    attself[(size_t)n*256 + q*16 + k] = e / sum;
}

// ------------------------- si (split out, row stride 2*H*D) ------------------
__global__ void si_kernel(const float* __restrict__ xe, const float* __restrict__ attself,
                          const float* __restrict__ attint, const float* __restrict__ att_factor,
                          __nv_bfloat16* __restrict__ spSi) {
    int n = blockIdx.x >> 4;
    int q = blockIdx.x & 15;
    int tid = threadIdx.x;
    __shared__ float xs[16*512];
    __shared__ float arow[H_*16];
    float factor = att_factor[0];
    for (int i = tid; i < 16*D_; i += 512) xs[i] = xe[(size_t)n*T_*D_ + i];
    if (tid < H_*16) {
        int h = tid >> 4, t = tid & 15;
        arow[tid] = attself[(size_t)n*256 + q*16 + t]
                  + factor * attint[((n*H_ + h)*16 + q)*16 + t];
    }
    __syncthreads();
    int d = tid;
    size_t row = (size_t)(n*T_ + q);
    #pragma unroll
    for (int h = 0; h < H_; h++) {
        float acc = 0.0f;
        #pragma unroll
        for (int t = 0; t < 16; t++) acc = fmaf(arow[h*16+t], xs[t*512 + d], acc);
        splitw(spSi, row*8192 + h*D_ + d, row*8192 + 4096 + h*D_ + d, acc);
    }
}

// ------------------------- prediction head -----------------------------------
__global__ void pred_kernel(const float* __restrict__ xe, const float* __restrict__ Wp,
                            const float* __restrict__ bp, float* __restrict__ out) {
    int idx = blockIdx.x * blockDim.x + threadIdx.x;
    if (idx >= N_*T_*2) return;
    int c = idx & 1;
    int t = (idx >> 1) & 15;
    int n = idx >> 5;
    float acc = bp[c];
    const float* xr = xe + ((size_t)(n*T_ + t))*D_;
    for (int d = 0; d < D_; d++) acc = fmaf(xr[d], Wp[d*2 + c], acc);
    for (int p = 0; p < 20; p++)
        out[(((size_t)p*T_ + t)*N_ + n)*2 + c] = acc;
}

// ---------------------------------------------------------------------------
static inline void convB(const float* W, __nv_bfloat16* Bq, int K, int Nw, int ldB) {
    convB_kernel<<<(K*Nw+255)/256, 256>>>(W, Bq, K, Nw, ldB);
}
static inline void gemm3(const __nv_bfloat16* A, const __nv_bfloat16* Bq,
                         float* C, __nv_bfloat16* Csp,
                         int M, int N, int K, int flags) {
    dim3 grid(N/128, M/128);
    gemm3_kernel<<<grid, 256>>>(A, Bq, C, Csp, M, N, K, flags);
}

extern "C" void kernel_launch(void* const* d_in, const int* in_sizes, int n_in,
                              void* d_out, int out_size) {
    const float* x        = (const float*)d_in[0];
    const float* neighbor = (const float*)d_in[1];
    const float* att_fac  = (const float*)d_in[2];
    const float* Wx       = (const float*)d_in[3];
    const float* bx       = (const float*)d_in[4];
    const float* Wn       = (const float*)d_in[5];
    const float* bn       = (const float*)d_in[6];
    const float* Wpred    = (const float*)d_in[7];
    const float* bpred    = (const float*)d_in[8];
    const float* WQ       = (const float*)d_in[9];
    const float* WK       = (const float*)d_in[10];
    const float* WV       = (const float*)d_in[11];
    const float* Wfc      = (const float*)d_in[12];
    const float* mha_g    = (const float*)d_in[13];
    const float* mha_b    = (const float*)d_in[14];
    const float* WSI      = (const float*)d_in[15];
    const float* ffs_w1   = (const float*)d_in[16];
    const float* ffs_w2   = (const float*)d_in[17];
    const float* ffs_g    = (const float*)d_in[18];
    const float* ffs_b    = (const float*)d_in[19];
    const float* ffi_w1   = (const float*)d_in[20];
    const float* ffi_w2   = (const float*)d_in[21];
    const float* ffi_g    = (const float*)d_in[22];
    const float* ffi_b    = (const float*)d_in[23];
    float* out = (float*)d_out;

    static float *pxf=0,*pnf=0,*ppe=0,*pxe=0,*pne=0,*pqkv=0,
                 *ptmpM=0,*pres=0,*pattn=0,*pattint=0,*pattself=0,
                 *pxnew=0,*ptmpS=0;
    static __nv_bfloat16 *pBq=0,*spNe=0,*spCtx=0,*spRes=0,*spHidM=0,
                         *spSi=0,*spXnew=0,*spHidS=0;
    static unsigned char* pmask=0;
    if (!pxf) {
        cudaGetSymbolAddress((void**)&pxf, g_xf);
        cudaGetSymbolAddress((void**)&pnf, g_nf);
        cudaGetSymbolAddress((void**)&pmask, g_mask);
        cudaGetSymbolAddress((void**)&ppe, g_pe);
        cudaGetSymbolAddress((void**)&pxe, g_xe);
        cudaGetSymbolAddress((void**)&pne, g_ne);
        cudaGetSymbolAddress((void**)&pqkv, g_QKV);
        cudaGetSymbolAddress((void**)&ptmpM, g_tmpM);
        cudaGetSymbolAddress((void**)&pres, g_res);
        cudaGetSymbolAddress((void**)&pattn, g_attn);
        cudaGetSymbolAddress((void**)&pattint, g_attint);
        cudaGetSymbolAddress((void**)&pattself, g_attself);
        cudaGetSymbolAddress((void**)&pxnew, g_xnew);
        cudaGetSymbolAddress((void**)&ptmpS, g_tmpS);
        cudaGetSymbolAddress((void**)&pBq, g_Bq);
        cudaGetSymbolAddress((void**)&spNe, g_spNe);
        cudaGetSymbolAddress((void**)&spCtx, g_spCtx);
        cudaGetSymbolAddress((void**)&spRes, g_spRes);
        cudaGetSymbolAddress((void**)&spHidM, g_spHidM);
        cudaGetSymbolAddress((void**)&spSi, g_spSi);
        cudaGetSymbolAddress((void**)&spXnew, g_spXnew);
        cudaGetSymbolAddress((void**)&spHidS, g_spHidS);
    }

    feat_kernel<<<(T_*N_*NN_+255)/256, 256>>>(x, neighbor, pxf, pnf, pmask);
    pe_kernel<<<(T_*D_+255)/256, 256>>>(ppe);
    xemb_kernel<<<(NTOKS*D_+255)/256, 256>>>(pxf, Wx, bx, ppe, pxe);
    nemb_kernel<<<(int)(((size_t)NTOKB*D_+255)/256), 256>>>(pnf, Wn, bn, ppe, pne, spNe);

    for (int l = 0; l < L_; l++) {
        const float* WQl  = WQ  + (size_t)l*D_*D_;
        const float* WKl  = WK  + (size_t)l*D_*D_;
        const float* WVl  = WV  + (size_t)l*D_*D_;
        const float* Wfcl = Wfc + (size_t)l*D_*D_;
        const float* WSIl = WSI + (size_t)l*(H_*D_)*D_;

        // fused QKV: Bq (2*512, 1536) with col blocks Q|K|V
        convB(WQl, pBq,        D_, D_, 1536);
        convB(WKl, pBq + 512,  D_, D_, 1536);
        convB(WVl, pBq + 1024, D_, D_, 1536);
        gemm3(spNe, pBq, pqkv, 0, NTOKB, 3*D_, D_, GF_F32);

        attn_kernel<<<NPAIR*H_, 256>>>(pqkv, pmask, spCtx, pattn);
        attmean_kernel<<<(N_*H_*256+255)/256, 256>>>(pattn, pattint);

        convB(Wfcl, pBq, D_, D_, D_);
        gemm3(spCtx, pBq, ptmpM, 0, NTOKB, D_, D_, GF_F32);
        add_ln_kernel<<<NTOKB, 256>>>(ptmpM, pne, mha_g + l*D_, mha_b + l*D_, pres, spRes);

        attself_kernel<<<N_, 256>>>(pxe, pattself);
        si_kernel<<<NTOKS, 512>>>(pxe, pattself, pattint, att_fac, spSi);

        convB(WSIl, pBq, H_*D_, D_, D_);
        gemm3(spSi, pBq, pxnew, spXnew, NTOKS, D_, H_*D_, GF_F32 | GF_SPLIT);

        convB(ffs_w1 + (size_t)l*D_*DFF_, pBq, D_, DFF_, DFF_);
        gemm3(spXnew, pBq, 0, spHidS, NTOKS, DFF_, D_, GF_RELU | GF_SPLIT);
        convB(ffs_w2 + (size_t)l*DFF_*D_, pBq, DFF_, D_, D_);
        gemm3(spHidS, pBq, ptmpS, 0, NTOKS, D_, DFF_, GF_F32);
        add_ln_kernel<<<NTOKS, 256>>>(ptmpS, pxnew, ffs_g + l*D_, ffs_b + l*D_, pxe, 0);

        convB(ffi_w1 + (size_t)l*D_*DFF_, pBq, D_, DFF_, DFF_);
        gemm3(spRes, pBq, 0, spHidM, NTOKB, DFF_, D_, GF_RELU | GF_SPLIT);
        convB(ffi_w2 + (size_t)l*DFF_*D_, pBq, DFF_, D_, D_);
        gemm3(spHidM, pBq, ptmpM, 0, NTOKB, D_, DFF_, GF_F32);
        add_ln_kernel<<<NTOKB, 256>>>(ptmpM, pres, ffi_g + l*D_, ffi_b + l*D_, pne,
                                      (l+1 < L_) ? spNe : 0);
    }

    pred_kernel<<<(N_*T_*2+255)/256, 256>>>(pxe, Wpred, bpred, out);
}

// round 10
// speedup vs baseline: 2.7245x; 1.0858x over previous
#include <cuda_runtime.h>
#include <cuda_bf16.h>
#include <math.h>
#include <float.h>
#include <stdint.h>

// ---------------------------------------------------------------------------
// SocialTrans: T=16, N=64, NN=32, D=512, H=8, DK=64, DFF=2048, L=2
// GEMMs via mma.sync bf16 split-precision (AhBh+AhBl+AlBh, fp32 accum).
// Split conversion fused into producers. GEMM: 4-stage cp.async, ldsm x4t,
// 2 CTAs/SM.
// ---------------------------------------------------------------------------
#define T_ 16
#define N_ 64
#define NN_ 32
#define D_ 512
#define H_ 8
#define DK_ 64
#define DFF_ 2048
#define L_ 2
#define NPAIR (N_*NN_)          // 2048
#define NTOKB (NPAIR*T_)        // 32768  neighbor tokens
#define NTOKS (N_*T_)           // 1024   self tokens

#define GF_RELU 1
#define GF_SPLIT 2
#define GF_F32 4

#define GSTG 4
#define GSMEM_BYTES (GSTG*16384)

// ------------------------- device scratch (static, no allocs) --------------
__device__ float g_xf  [T_*N_*4];
__device__ float g_nf  [T_*N_*NN_*3];
__device__ unsigned char g_mask[NPAIR*T_];
__device__ float g_pe  [T_*D_];
__device__ float g_xe  [NTOKS*D_];
__device__ float g_ne  [NTOKB*D_];
__device__ float g_QKV [NTOKB*3*D_];
__device__ float g_tmpM[NTOKB*D_];
__device__ float g_res [NTOKB*D_];
__device__ float g_attn[NPAIR*H_*T_*T_];
__device__ float g_attint[N_*H_*T_*T_];
__device__ float g_attself[N_*T_*T_];
__device__ float g_xnew[NTOKS*D_];
__device__ float g_tmpS[NTOKS*D_];
// split (hi|lo) bf16 buffers, row stride = 2K
__device__ __nv_bfloat16 g_spNe  [NTOKB*2*D_];
__device__ __nv_bfloat16 g_spCtx [NTOKB*2*D_];
__device__ __nv_bfloat16 g_spRes [NTOKB*2*D_];
__device__ __nv_bfloat16 g_spHidM[(size_t)NTOKB*2*DFF_];
__device__ __nv_bfloat16 g_spSi  [NTOKS*2*H_*D_];
__device__ __nv_bfloat16 g_spXnew[NTOKS*2*D_];
__device__ __nv_bfloat16 g_spHidS[NTOKS*2*DFF_];
__device__ __nv_bfloat16 g_Bq[4194304];     // weights: max 2K*N = 8192*512 (QKV: 1024*1536)

// ------------------------- PTX helpers --------------------------------------
__device__ __forceinline__ uint32_t smem_u32(const void* p) {
    uint32_t a;
    asm("{ .reg .u64 t; cvta.to.shared.u64 t, %1; cvt.u32.u64 %0, t; }" : "=r"(a) : "l"(p));
    return a;
}
__device__ __forceinline__ void cp_async16(uint32_t saddr, const void* gaddr) {
    asm volatile("cp.async.cg.shared.global [%0], [%1], 16;" :: "r"(saddr), "l"(gaddr));
}
__device__ __forceinline__ void cp_commit() { asm volatile("cp.async.commit_group;" ::: "memory"); }
__device__ __forceinline__ void cp_wait2()  { asm volatile("cp.async.wait_group 2;" ::: "memory"); }

__device__ __forceinline__ void ldsm4(uint32_t* d, uint32_t a) {
    asm volatile("ldmatrix.sync.aligned.m8n8.x4.shared.b16 {%0,%1,%2,%3}, [%4];"
        : "=r"(d[0]), "=r"(d[1]), "=r"(d[2]), "=r"(d[3]) : "r"(a));
}
__device__ __forceinline__ void ldsm4t(uint32_t* d, uint32_t a) {
    asm volatile("ldmatrix.sync.aligned.m8n8.x4.trans.shared.b16 {%0,%1,%2,%3}, [%4];"
        : "=r"(d[0]), "=r"(d[1]), "=r"(d[2]), "=r"(d[3]) : "r"(a));
}
__device__ __forceinline__ void mma16816(float* d, const uint32_t* a, const uint32_t* b) {
    asm volatile("mma.sync.aligned.m16n8k16.row.col.f32.bf16.bf16.f32 "
        "{%0,%1,%2,%3}, {%4,%5,%6,%7}, {%8,%9}, {%0,%1,%2,%3};"
        : "+f"(d[0]), "+f"(d[1]), "+f"(d[2]), "+f"(d[3])
        : "r"(a[0]), "r"(a[1]), "r"(a[2]), "r"(a[3]), "r"(b[0]), "r"(b[1]));
}
__device__ __forceinline__ void split2(float x, float y, __nv_bfloat162& hi, __nv_bfloat162& lo) {
    __nv_bfloat16 hx = __float2bfloat16(x);
    __nv_bfloat16 hy = __float2bfloat16(y);
    hi = __nv_bfloat162(hx, hy);
    lo = __nv_bfloat162(__float2bfloat16(x - __bfloat162float(hx)),
                        __float2bfloat16(y - __bfloat162float(hy)));
}

// ------------------------- weight conversion ---------------------------------
// Bq (2K, ldB) = [Bh ; Bl] from W (K, Nw) row-major; column offset via pointer.
__global__ void convB_kernel(const float* __restrict__ W, __nv_bfloat16* __restrict__ Bq,
                             int K, int Nw, int ldB) {
    int idx = blockIdx.x * blockDim.x + threadIdx.x;   // k*Nw + n
    if (idx >= K*Nw) return;
    int k = idx / Nw, n = idx - k*Nw;
    float a = W[idx];
    __nv_bfloat16 h = __float2bfloat16(a);
    __nv_bfloat16 l = __float2bfloat16(a - __bfloat162float(h));
    Bq[(size_t)k*ldB + n]       = h;
    Bq[(size_t)(K + k)*ldB + n] = l;
}

// ------------------------- mma.sync GEMM -------------------------------------
// C(M,N) = A(M,K) @ B(K,N): 3 passes AhBh + AhBl + AlBh.
// A (M,2K) m-major split; B (2K,N) k-major split.  M%128==0, N%128==0, K%32==0.
// Outputs: GF_F32 -> C fp32 (ld N); GF_SPLIT -> Csp (M,2N) split bf16.
__global__ void __launch_bounds__(256, 2)
gemm3_kernel(const __nv_bfloat16* __restrict__ A, const __nv_bfloat16* __restrict__ B,
             float* __restrict__ C, __nv_bfloat16* __restrict__ Csp,
             int M, int N, int K, int flags) {
    extern __shared__ __align__(1024) char smem[];   // GSTG stages x (A 8KB + B 8KB)
    int tid = threadIdx.x;
    int lane = tid & 31, wid = tid >> 5;
    int warp_m = wid & 3, warp_n = wid >> 2;
    int mBase = blockIdx.y * 128, nBase = blockIdx.x * 128;
    int ldA = 2*K, ldB = N;
    int KTp = K >> 5, KT = 3*KTp;
    uint32_t sbase = smem_u32(smem);

    #define LOAD_STAGE(g, s) do { \
        int p_ = (g)/KTp, kt_ = (g) - p_*KTp; \
        int ka_ = ((p_==2)?K:0) + (kt_<<5); \
        int kb_ = ((p_==1)?K:0) + (kt_<<5); \
        uint32_t sa_ = sbase + (s)*16384; \
        uint32_t sb_ = sa_ + 8192; \
        const __nv_bfloat16* Ag_ = A + (size_t)mBase*ldA + ka_; \
        const __nv_bfloat16* Bg_ = B + (size_t)kb_*ldB + nBase; \
        _Pragma("unroll") \
        for (int i_ = 0; i_ < 2; i_++) { \
            int id_ = tid + i_*256; int r_ = id_ >> 2, c_ = id_ & 3; \
            cp_async16(sa_ + r_*64 + ((c_ ^ ((r_>>1)&3)) << 4), \
                       Ag_ + (size_t)r_*ldA + c_*8); \
        } \
        _Pragma("unroll") \
        for (int i_ = 0; i_ < 2; i_++) { \
            int id_ = tid + i_*256; int r_ = id_ >> 4, c_ = id_ & 15; \
            cp_async16(sb_ + r_*256 + ((c_ ^ (r_&7)) << 4), \
                       Bg_ + (size_t)r_*ldB + c_*8); \
        } \
    } while (0)

    LOAD_STAGE(0, 0); cp_commit();
    LOAD_STAGE(1, 1); cp_commit();
    LOAD_STAGE(2, 2); cp_commit();

    float acc[2][8][4];
    #pragma unroll
    for (int mi = 0; mi < 2; mi++)
        #pragma unroll
        for (int ni = 0; ni < 8; ni++)
            #pragma unroll
            for (int j = 0; j < 4; j++) acc[mi][ni][j] = 0.0f;

    for (int g = 0; g < KT; g++) {
        cp_wait2();
        __syncthreads();
        uint32_t sa = sbase + (g & (GSTG-1))*16384;
        uint32_t sb = sa + 8192;
        #pragma unroll
        for (int kh = 0; kh < 2; kh++) {
            uint32_t af[2][4];
            #pragma unroll
            for (int mi = 0; mi < 2; mi++) {
                int r = warp_m*32 + mi*16 + (lane & 15);
                int c = kh*2 + (lane >> 4);
                ldsm4(af[mi], sa + r*64 + ((c ^ ((r>>1)&3)) << 4));
            }
            // B: x4.trans covers n16 per load (regs {0,1}=n8 group c, {2,3}=group c+1)
            uint32_t bq[4][4];
            #pragma unroll
            for (int ni2 = 0; ni2 < 4; ni2++) {
                int r = kh*16 + (lane & 15);
                int c = warp_n*8 + ni2*2 + (lane >> 4);
                ldsm4t(bq[ni2], sb + r*256 + ((c ^ (r&7)) << 4));
            }
            #pragma unroll
            for (int mi = 0; mi < 2; mi++)
                #pragma unroll
                for (int ni2 = 0; ni2 < 4; ni2++) {
                    mma16816(acc[mi][2*ni2],   af[mi], &bq[ni2][0]);
                    mma16816(acc[mi][2*ni2+1], af[mi], &bq[ni2][2]);
                }
        }
        if (g + 3 < KT) LOAD_STAGE(g + 3, (g + 3) & (GSTG-1));
        cp_commit();
    }

    // epilogue
    int relu = flags & GF_RELU;
    #pragma unroll
    for (int mi = 0; mi < 2; mi++) {
        int r0 = mBase + warp_m*32 + mi*16 + (lane >> 2);
        #pragma unroll
        for (int ni = 0; ni < 8; ni++) {
            int col = nBase + warp_n*64 + ni*8 + (lane & 3)*2;
            float2 v0 = make_float2(acc[mi][ni][0], acc[mi][ni][1]);
            float2 v1 = make_float2(acc[mi][ni][2], acc[mi][ni][3]);
            if (relu) {
                v0.x = fmaxf(v0.x, 0.f); v0.y = fmaxf(v0.y, 0.f);
                v1.x = fmaxf(v1.x, 0.f); v1.y = fmaxf(v1.y, 0.f);
            }
            if (flags & GF_F32) {
                *(float2*)(C + (size_t)r0*N + col)     = v0;
                *(float2*)(C + (size_t)(r0+8)*N + col) = v1;
            }
            if (flags & GF_SPLIT) {
                __nv_bfloat162 hi, lo;
                split2(v0.x, v0.y, hi, lo);
                *(__nv_bfloat162*)(Csp + (size_t)r0*2*N + col)     = hi;
                *(__nv_bfloat162*)(Csp + (size_t)r0*2*N + N + col) = lo;
                split2(v1.x, v1.y, hi, lo);
                *(__nv_bfloat162*)(Csp + (size_t)(r0+8)*2*N + col)     = hi;
                *(__nv_bfloat162*)(Csp + (size_t)(r0+8)*2*N + N + col) = lo;
            }
        }
    }
    #undef LOAD_STAGE
}

// ------------------------- helpers -----------------------------------------
__device__ __forceinline__ float n2n(float v) {
    if (isnan(v)) return 0.0f;
    if (isinf(v)) return v > 0.0f ? 3.4028235e38f : -3.4028235e38f;
    return v;
}
__device__ __forceinline__ void splitw(__nv_bfloat16* sp, size_t hi_idx, size_t lo_idx, float v) {
    __nv_bfloat16 h = __float2bfloat16(v);
    sp[hi_idx] = h;
    sp[lo_idx] = __float2bfloat16(v - __bfloat162float(h));
}

// ------------------------- feature kernel -----------------------------------
__global__ void feat_kernel(const float* __restrict__ x, const float* __restrict__ nb,
                            float* __restrict__ xf, float* __restrict__ nf,
                            unsigned char* __restrict__ mask) {
    int idx = blockIdx.x * blockDim.x + threadIdx.x;
    if (idx >= T_*N_*NN_) return;
    int nn = idx & (NN_-1);
    int rem = idx >> 5;
    int n  = rem & (N_-1);
    int t  = rem >> 6;
    const float* xr = x + ((size_t)t*N_ + n)*6;
    float px = xr[0], py = xr[1];
    float vx, vy;
    if (t == 0) {
        const float* x1 = x + ((size_t)1*N_ + n)*6;
        vx = x1[2]; vy = x1[3];
    } else {
        const float* xp = x + ((size_t)(t-1)*N_ + n)*6;
        vx = px - xp[0]; vy = py - xp[1];
    }
    const float* nr = nb + (((size_t)t*N_ + n)*NN_ + nn)*4;
    float dpx = nr[0]-px, dpy = nr[1]-py;
    float dvx = nr[2]-vx, dvy = nr[3]-vy;
    float dist = sqrtf(dpx*dpx + dpy*dpy);
    mask[(n*NN_ + nn)*T_ + t] = (dist <= 2.0f) ? 1 : 0;
    float nv = sqrtf(vx*vx + vy*vy);
    float bearing = (dpx*vx + dpy*vy) / (dist*nv);
    if (isnan(bearing)) bearing = 0.0f;
    float ndv = sqrtf(dvx*dvx + dvy*dvy);
    float tau = -(dpx*dvx + dpy*dvy) / ndv;
    if (isnan(tau)) tau = 0.0f;
    tau = fminf(fmaxf(tau, 0.0f), 7.0f);
    float mxx = dpx + tau*dvx, myy = dpy + tau*dvy;
    float mpd = sqrtf(mxx*mxx + myy*myy);
    float* o = nf + (size_t)idx*3;
    o[0] = n2n(dist); o[1] = n2n(bearing); o[2] = n2n(mpd);
    if (nn == 0) {
        float vel = sqrtf(xr[2]*xr[2] + xr[3]*xr[3]);
        float ang = atanf(xr[5]/xr[4]);
        float* xo = xf + ((size_t)t*N_ + n)*4;
        xo[0] = n2n(xr[0]); xo[1] = n2n(xr[1]); xo[2] = n2n(vel); xo[3] = n2n(ang);
    }
}

// ------------------------- positional encoding -------------------------------
__global__ void pe_kernel(float* __restrict__ pe) {
    int i = blockIdx.x * blockDim.x + threadIdx.x;
    if (i >= T_*D_) return;
    int t = i >> 9, d = i & (D_-1);
    double expo = (double)(d & ~1) / (double)D_;
    float div = (float)exp(expo * 9.210340371976184);
    float arg = (float)t * div;
    pe[i] = (d & 1) ? (float)cos((double)arg) : (float)sin((double)arg);
}

// ------------------------- embeddings ----------------------------------------
__global__ void xemb_kernel(const float* __restrict__ xf, const float* __restrict__ Wx,
                            const float* __restrict__ bx, const float* __restrict__ pe,
                            float* __restrict__ xe) {
    int i = blockIdx.x * blockDim.x + threadIdx.x;
    if (i >= NTOKS*D_) return;
    int d = i & (D_-1);
    int tok = i >> 9;
    int t = tok >> 6, n = tok & (N_-1);
    const float* f = xf + (size_t)tok*4;
    float acc = bx[d] + pe[t*D_ + d];
    #pragma unroll
    for (int k = 0; k < 4; k++) acc = fmaf(f[k], Wx[k*D_ + d], acc);
    xe[((size_t)(n*T_ + t))*D_ + d] = acc;
}

// writes ne fp32 (residual use) + split bf16 (GEMM A use)
__global__ void nemb_kernel(const float* __restrict__ nf, const float* __restrict__ Wn,
                            const float* __restrict__ bn, const float* __restrict__ pe,
                            float* __restrict__ ne, __nv_bfloat16* __restrict__ sp) {
    size_t i = (size_t)blockIdx.x * blockDim.x + threadIdx.x;
    if (i >= (size_t)NTOKB*D_) return;
    int d = (int)(i & (D_-1));
    int tok = (int)(i >> 9);
    int nn = tok & (NN_-1);
    int rem = tok >> 5;
    int n = rem & (N_-1);
    int t = rem >> 6;
    const float* f = nf + (size_t)tok*3;
    float acc = bn[d] + pe[t*D_ + d];
    acc = fmaf(f[0], Wn[d], acc);
    acc = fmaf(f[1], Wn[D_ + d], acc);
    acc = fmaf(f[2], Wn[2*D_ + d], acc);
    size_t row = (size_t)(n*NN_ + nn)*T_ + t;
    ne[row*D_ + d] = acc;
    splitw(sp, row*2*D_ + d, row*2*D_ + D_ + d, acc);
}

// ------------------------- neighbor attention --------------------------------
// QKV fused buffer: row stride 1536, Q at +0, K at +512, V at +1024
// ctx written directly as split bf16 (row stride 1024)
__global__ void attn_kernel(const float* __restrict__ QKV, const unsigned char* __restrict__ mask,
                            __nv_bfloat16* __restrict__ spCtx, float* __restrict__ attn_out) {
    int b = blockIdx.x;
    int h = b & (H_-1);
    int pair = b >> 3;
    int tid = threadIdx.x;
    __shared__ float q[16*68], k[16*68], v[16*68];
    __shared__ float at[16*17];
    size_t base = (size_t)pair*T_*1536 + h*DK_;
    for (int i = tid; i < 16*64; i += 256) {
        int t = i >> 6, d = i & 63;
        q[t*68+d] = QKV[base + (size_t)t*1536 + d];
        k[t*68+d] = QKV[base + (size_t)t*1536 + 512 + d];
        v[t*68+d] = QKV[base + (size_t)t*1536 + 1024 + d];
    }
    __syncthreads();
    int qt = tid >> 4, kt = tid & 15;
    float s = 0.0f;
    #pragma unroll
    for (int d = 0; d < 64; d++) s = fmaf(q[qt*68+d], k[kt*68+d], s);
    s *= 0.125f;
    if (!mask[pair*T_ + qt]) s = -1e9f;
    float mx = s;
    #pragma unroll
    for (int o = 8; o; o >>= 1) mx = fmaxf(mx, __shfl_xor_sync(0xffffffffu, mx, o));
    float e = expf(s - mx);
    float sum = e;
    #pragma unroll
    for (int o = 8; o; o >>= 1) sum += __shfl_xor_sync(0xffffffffu, sum, o);
    float a = e / sum;
    at[qt*17 + kt] = a;
    attn_out[(size_t)b*256 + qt*16 + kt] = a;
    __syncthreads();
    for (int i = tid; i < 16*64; i += 256) {
        int t = i >> 6, d = i & 63;
        float acc = 0.0f;
        #pragma unroll
        for (int kk = 0; kk < 16; kk++) acc = fmaf(at[t*17+kk], v[kk*68+d], acc);
        size_t row = (size_t)pair*T_ + t;
        splitw(spCtx, row*1024 + h*DK_ + d, row*1024 + 512 + h*DK_ + d, acc);
    }
}

__global__ void attmean_kernel(const float* __restrict__ attn, float* __restrict__ attint) {
    int i = blockIdx.x * blockDim.x + threadIdx.x;
    if (i >= N_*H_*256) return;
    int qk = i & 255;
    int h  = (i >> 8) & (H_-1);
    int n  = i >> 11;
    float s = 0.0f;
    #pragma unroll 4
    for (int nn = 0; nn < NN_; nn++)
        s += attn[(((size_t)(n*NN_ + nn)*H_ + h)*256) + qk];
    attint[i] = s * (1.0f/32.0f);
}

// ------------------------- add + layernorm (optional split out) --------------
__global__ void add_ln_kernel(const float* __restrict__ X, const float* __restrict__ R,
                              const float* __restrict__ g, const float* __restrict__ b,
                              float* __restrict__ out, __nv_bfloat16* __restrict__ sp) {
    int row = blockIdx.x, tid = threadIdx.x;
    size_t off = (size_t)row*D_;
    float x0 = X[off+tid]     + R[off+tid];
    float x1 = X[off+256+tid] + R[off+256+tid];
    __shared__ float red[8], red2[8];
    float s = x0 + x1;
    #pragma unroll
    for (int o = 16; o; o >>= 1) s += __shfl_xor_sync(0xffffffffu, s, o);
    if ((tid & 31) == 0) red[tid >> 5] = s;
    __syncthreads();
    float tot = 0.0f;
    #pragma unroll
    for (int i = 0; i < 8; i++) tot += red[i];
    float m = tot * (1.0f/512.0f);
    float d0 = x0 - m, d1 = x1 - m;
    float vs = d0*d0 + d1*d1;
    #pragma unroll
    for (int o = 16; o; o >>= 1) vs += __shfl_xor_sync(0xffffffffu, vs, o);
    if ((tid & 31) == 0) red2[tid >> 5] = vs;
    __syncthreads();
    float vtot = 0.0f;
    #pragma unroll
    for (int i = 0; i < 8; i++) vtot += red2[i];
    float inv = 1.0f / sqrtf(vtot * (1.0f/512.0f) + 1e-5f);
    float o0 = d0*inv*g[tid]     + b[tid];
    float o1 = d1*inv*g[tid+256] + b[tid+256];
    out[off+tid]     = o0;
    out[off+256+tid] = o1;
    if (sp) {
        size_t sro = (size_t)row*1024;
        splitw(sp, sro + tid,       sro + 512 + tid,       o0);
        splitw(sp, sro + 256 + tid, sro + 768 + tid,       o1);
    }
}

// ------------------------- self attention ------------------------------------
__global__ void attself_kernel(const float* __restrict__ xe, float* __restrict__ attself) {
    int n = blockIdx.x;
    int tid = threadIdx.x;
    __shared__ float xs[16*516];
    for (int i = tid; i < 16*D_; i += 256) {
        int t = i >> 9, d = i & (D_-1);
        xs[t*516 + d] = xe[((size_t)(n*T_ + t))*D_ + d];
    }
    __syncthreads();
    int q = tid >> 4, k = tid & 15;
    float s = 0.0f;
    for (int d = 0; d < D_; d++) s = fmaf(xs[q*516+d], xs[k*516+d], s);
    s *= 0.04419417382415922f;
    float mx = s;
    #pragma unroll
    for (int o = 8; o; o >>= 1) mx = fmaxf(mx, __shfl_xor_sync(0xffffffffu, mx, o));
    float e = expf(s - mx);
    float sum = e;
    #pragma unroll
    for (int o = 8; o; o >>= 1) sum += __shfl_xor_sync(0xffffffffu, sum, o);
    attself[(size_t)n*256 + q*16 + k] = e / sum;
}

// ------------------------- si (split out, row stride 2*H*D) ------------------
__global__ void si_kernel(const float* __restrict__ xe, const float* __restrict__ attself,
                          const float* __restrict__ attint, const float* __restrict__ att_factor,
                          __nv_bfloat16* __restrict__ spSi) {
    int n = blockIdx.x >> 4;
    int q = blockIdx.x & 15;
    int tid = threadIdx.x;
    __shared__ float xs[16*512];
    __shared__ float arow[H_*16];
    float factor = att_factor[0];
    for (int i = tid; i < 16*D_; i += 512) xs[i] = xe[(size_t)n*T_*D_ + i];
    if (tid < H_*16) {
        int h = tid >> 4, t = tid & 15;
        arow[tid] = attself[(size_t)n*256 + q*16 + t]
                  + factor * attint[((n*H_ + h)*16 + q)*16 + t];
    }
    __syncthreads();
    int d = tid;
    size_t row = (size_t)(n*T_ + q);
    #pragma unroll
    for (int h = 0; h < H_; h++) {
        float acc = 0.0f;
        #pragma unroll
        for (int t = 0; t < 16; t++) acc = fmaf(arow[h*16+t], xs[t*512 + d], acc);
        splitw(spSi, row*8192 + h*D_ + d, row*8192 + 4096 + h*D_ + d, acc);
    }
}

// ------------------------- prediction head -----------------------------------
__global__ void pred_kernel(const float* __restrict__ xe, const float* __restrict__ Wp,
                            const float* __restrict__ bp, float* __restrict__ out) {
    int idx = blockIdx.x * blockDim.x + threadIdx.x;
    if (idx >= N_*T_*2) return;
    int c = idx & 1;
    int t = (idx >> 1) & 15;
    int n = idx >> 5;
    float acc = bp[c];
    const float* xr = xe + ((size_t)(n*T_ + t))*D_;
    for (int d = 0; d < D_; d++) acc = fmaf(xr[d], Wp[d*2 + c], acc);
    for (int p = 0; p < 20; p++)
        out[(((size_t)p*T_ + t)*N_ + n)*2 + c] = acc;
}

// ---------------------------------------------------------------------------
static inline void convB(const float* W, __nv_bfloat16* Bq, int K, int Nw, int ldB) {
    convB_kernel<<<(K*Nw+255)/256, 256>>>(W, Bq, K, Nw, ldB);
}
static inline void gemm3(const __nv_bfloat16* A, const __nv_bfloat16* Bq,
                         float* C, __nv_bfloat16* Csp,
                         int M, int N, int K, int flags) {
    dim3 grid(N/128, M/128);
    gemm3_kernel<<<grid, 256, GSMEM_BYTES>>>(A, Bq, C, Csp, M, N, K, flags);
}

extern "C" void kernel_launch(void* const* d_in, const int* in_sizes, int n_in,
                              void* d_out, int out_size) {
    const float* x        = (const float*)d_in[0];
    const float* neighbor = (const float*)d_in[1];
    const float* att_fac  = (const float*)d_in[2];
    const float* Wx       = (const float*)d_in[3];
    const float* bx       = (const float*)d_in[4];
    const float* Wn       = (const float*)d_in[5];
    const float* bn       = (const float*)d_in[6];
    const float* Wpred    = (const float*)d_in[7];
    const float* bpred    = (const float*)d_in[8];
    const float* WQ       = (const float*)d_in[9];
    const float* WK       = (const float*)d_in[10];
    const float* WV       = (const float*)d_in[11];
    const float* Wfc      = (const float*)d_in[12];
    const float* mha_g    = (const float*)d_in[13];
    const float* mha_b    = (const float*)d_in[14];
    const float* WSI      = (const float*)d_in[15];
    const float* ffs_w1   = (const float*)d_in[16];
    const float* ffs_w2   = (const float*)d_in[17];
    const float* ffs_g    = (const float*)d_in[18];
    const float* ffs_b    = (const float*)d_in[19];
    const float* ffi_w1   = (const float*)d_in[20];
    const float* ffi_w2   = (const float*)d_in[21];
    const float* ffi_g    = (const float*)d_in[22];
    const float* ffi_b    = (const float*)d_in[23];
    float* out = (float*)d_out;

    static float *pxf=0,*pnf=0,*ppe=0,*pxe=0,*pne=0,*pqkv=0,
                 *ptmpM=0,*pres=0,*pattn=0,*pattint=0,*pattself=0,
                 *pxnew=0,*ptmpS=0;
    static __nv_bfloat16 *pBq=0,*spNe=0,*spCtx=0,*spRes=0,*spHidM=0,
                         *spSi=0,*spXnew=0,*spHidS=0;
    static unsigned char* pmask=0;
    if (!pxf) {
        cudaGetSymbolAddress((void**)&pxf, g_xf);
        cudaGetSymbolAddress((void**)&pnf, g_nf);
        cudaGetSymbolAddress((void**)&pmask, g_mask);
        cudaGetSymbolAddress((void**)&ppe, g_pe);
        cudaGetSymbolAddress((void**)&pxe, g_xe);
        cudaGetSymbolAddress((void**)&pne, g_ne);
        cudaGetSymbolAddress((void**)&pqkv, g_QKV);
        cudaGetSymbolAddress((void**)&ptmpM, g_tmpM);
        cudaGetSymbolAddress((void**)&pres, g_res);
        cudaGetSymbolAddress((void**)&pattn, g_attn);
        cudaGetSymbolAddress((void**)&pattint, g_attint);
        cudaGetSymbolAddress((void**)&pattself, g_attself);
        cudaGetSymbolAddress((void**)&pxnew, g_xnew);
        cudaGetSymbolAddress((void**)&ptmpS, g_tmpS);
        cudaGetSymbolAddress((void**)&pBq, g_Bq);
        cudaGetSymbolAddress((void**)&spNe, g_spNe);
        cudaGetSymbolAddress((void**)&spCtx, g_spCtx);
        cudaGetSymbolAddress((void**)&spRes, g_spRes);
        cudaGetSymbolAddress((void**)&spHidM, g_spHidM);
        cudaGetSymbolAddress((void**)&spSi, g_spSi);
        cudaGetSymbolAddress((void**)&spXnew, g_spXnew);
        cudaGetSymbolAddress((void**)&spHidS, g_spHidS);
        cudaFuncSetAttribute(gemm3_kernel, cudaFuncAttributeMaxDynamicSharedMemorySize,
                             GSMEM_BYTES);
    }

    feat_kernel<<<(T_*N_*NN_+255)/256, 256>>>(x, neighbor, pxf, pnf, pmask);
    pe_kernel<<<(T_*D_+255)/256, 256>>>(ppe);
    xemb_kernel<<<(NTOKS*D_+255)/256, 256>>>(pxf, Wx, bx, ppe, pxe);
    nemb_kernel<<<(int)(((size_t)NTOKB*D_+255)/256), 256>>>(pnf, Wn, bn, ppe, pne, spNe);

    for (int l = 0; l < L_; l++) {
        const float* WQl  = WQ  + (size_t)l*D_*D_;
        const float* WKl  = WK  + (size_t)l*D_*D_;
        const float* WVl  = WV  + (size_t)l*D_*D_;
        const float* Wfcl = Wfc + (size_t)l*D_*D_;
        const float* WSIl = WSI + (size_t)l*(H_*D_)*D_;

        // fused QKV: Bq (2*512, 1536) with col blocks Q|K|V
        convB(WQl, pBq,        D_, D_, 1536);
        convB(WKl, pBq + 512,  D_, D_, 1536);
        convB(WVl, pBq + 1024, D_, D_, 1536);
        gemm3(spNe, pBq, pqkv, 0, NTOKB, 3*D_, D_, GF_F32);

        attn_kernel<<<NPAIR*H_, 256>>>(pqkv, pmask, spCtx, pattn);
        attmean_kernel<<<(N_*H_*256+255)/256, 256>>>(pattn, pattint);

        convB(Wfcl, pBq, D_, D_, D_);
        gemm3(spCtx, pBq, ptmpM, 0, NTOKB, D_, D_, GF_F32);
        add_ln_kernel<<<NTOKB, 256>>>(ptmpM, pne, mha_g + l*D_, mha_b + l*D_, pres, spRes);

        attself_kernel<<<N_, 256>>>(pxe, pattself);
        si_kernel<<<NTOKS, 512>>>(pxe, pattself, pattint, att_fac, spSi);

        convB(WSIl, pBq, H_*D_, D_, D_);
        gemm3(spSi, pBq, pxnew, spXnew, NTOKS, D_, H_*D_, GF_F32 | GF_SPLIT);

        convB(ffs_w1 + (size_t)l*D_*DFF_, pBq, D_, DFF_, DFF_);
        gemm3(spXnew, pBq, 0, spHidS, NTOKS, DFF_, D_, GF_RELU | GF_SPLIT);
        convB(ffs_w2 + (size_t)l*DFF_*D_, pBq, DFF_, D_, D_);
        gemm3(spHidS, pBq, ptmpS, 0, NTOKS, D_, DFF_, GF_F32);
        add_ln_kernel<<<NTOKS, 256>>>(ptmpS, pxnew, ffs_g + l*D_, ffs_b + l*D_, pxe, 0);

        convB(ffi_w1 + (size_t)l*D_*DFF_, pBq, D_, DFF_, DFF_);
        gemm3(spRes, pBq, 0, spHidM, NTOKB, DFF_, D_, GF_RELU | GF_SPLIT);
        convB(ffi_w2 + (size_t)l*DFF_*D_, pBq, DFF_, D_, D_);
        gemm3(spHidM, pBq, ptmpM, 0, NTOKB, D_, DFF_, GF_F32);
        add_ln_kernel<<<NTOKB, 256>>>(ptmpM, pres, ffi_g + l*D_, ffi_b + l*D_, pne,
                                      (l+1 < L_) ? spNe : 0);
    }

    pred_kernel<<<(N_*T_*2+255)/256, 256>>>(pxe, Wpred, bpred, out);
}

// round 14
// speedup vs baseline: 2.7863x; 1.0227x over previous
#include <cuda_runtime.h>
#include <cuda_bf16.h>
#include <math.h>
#include <float.h>
#include <stdint.h>

// ---------------------------------------------------------------------------
// SocialTrans: T=16, N=64, NN=32, D=512, H=8, DK=64, DFF=2048, L=2
// GEMMs via mma.sync bf16 split-precision (AhBh+AhBl+AlBh, fp32 accum).
// k64 stages, 3-stage cp.async pipeline, 2 CTAs/SM, pre-converted weights.
// ---------------------------------------------------------------------------
#define T_ 16
#define N_ 64
#define NN_ 32
#define D_ 512
#define H_ 8
#define DK_ 64
#define DFF_ 2048
#define L_ 2
#define NPAIR (N_*NN_)          // 2048
#define NTOKB (NPAIR*T_)        // 32768  neighbor tokens
#define NTOKS (N_*T_)           // 1024   self tokens

#define GF_RELU 1
#define GF_SPLIT 2
#define GF_F32 4

#define GSTG 3
#define STGB 32768              // stage bytes: A 16KB + B 16KB
#define GSMEM_BYTES (GSTG*STGB)

// weight arena offsets (bf16 elements, per layer)
#define WOFF_QKV 0
#define WSZ_QKV  (1024*1536)
#define WOFF_FC  (WOFF_QKV + WSZ_QKV)
#define WSZ_FC   (1024*512)
#define WOFF_SI  (WOFF_FC + WSZ_FC)
#define WSZ_SI   (8192*512)
#define WOFF_FS1 (WOFF_SI + WSZ_SI)
#define WSZ_FS1  (1024*2048)
#define WOFF_FS2 (WOFF_FS1 + WSZ_FS1)
#define WSZ_FS2  (4096*512)
#define WOFF_FI1 (WOFF_FS2 + WSZ_FS2)
#define WSZ_FI1  (1024*2048)
#define WOFF_FI2 (WOFF_FI1 + WSZ_FI1)
#define WSZ_FI2  (4096*512)
#define WSZ_LAYER (WOFF_FI2 + WSZ_FI2)

// ------------------------- device scratch (static, no allocs) --------------
__device__ float g_xf  [T_*N_*4];
__device__ float g_nf  [T_*N_*NN_*3];
__device__ unsigned char g_mask[NPAIR*T_];
__device__ float g_pe  [T_*D_];
__device__ float g_xe  [NTOKS*D_];
__device__ float g_ne  [NTOKB*D_];
__device__ float g_QKV [NTOKB*3*D_];
__device__ float g_tmpM[NTOKB*D_];
__device__ float g_res [NTOKB*D_];
__device__ float g_attn[NPAIR*H_*T_*T_];
__device__ float g_attint[N_*H_*T_*T_];
__device__ float g_attself[N_*T_*T_];
__device__ float g_xnew[NTOKS*D_];
__device__ float g_tmpS[NTOKS*D_];
// split (hi|lo) bf16 buffers, row stride = 2K
__device__ __nv_bfloat16 g_spNe  [NTOKB*2*D_];
__device__ __nv_bfloat16 g_spCtx [NTOKB*2*D_];
__device__ __nv_bfloat16 g_spRes [NTOKB*2*D_];
__device__ __nv_bfloat16 g_spHidM[(size_t)NTOKB*2*DFF_];
__device__ __nv_bfloat16 g_spSi  [NTOKS*2*H_*D_];
__device__ __nv_bfloat16 g_spXnew[NTOKS*2*D_];
__device__ __nv_bfloat16 g_spHidS[NTOKS*2*DFF_];
__device__ __nv_bfloat16 g_Bw[(size_t)L_*WSZ_LAYER];   // pre-converted weights

// ------------------------- PTX helpers --------------------------------------
__device__ __forceinline__ uint32_t smem_u32(const void* p) {
    uint32_t a;
    asm("{ .reg .u64 t; cvta.to.shared.u64 t, %1; cvt.u32.u64 %0, t; }" : "=r"(a) : "l"(p));
    return a;
}
__device__ __forceinline__ void cp_async16(uint32_t saddr, const void* gaddr) {
    asm volatile("cp.async.cg.shared.global [%0], [%1], 16;" :: "r"(saddr), "l"(gaddr));
}
__device__ __forceinline__ void cp_commit() { asm volatile("cp.async.commit_group;" ::: "memory"); }
__device__ __forceinline__ void cp_wait1()  { asm volatile("cp.async.wait_group 1;" ::: "memory"); }

__device__ __forceinline__ void ldsm4(uint32_t* d, uint32_t a) {
    asm volatile("ldmatrix.sync.aligned.m8n8.x4.shared.b16 {%0,%1,%2,%3}, [%4];"
        : "=r"(d[0]), "=r"(d[1]), "=r"(d[2]), "=r"(d[3]) : "r"(a));
}
__device__ __forceinline__ void ldsm4t(uint32_t* d, uint32_t a) {
    asm volatile("ldmatrix.sync.aligned.m8n8.x4.trans.shared.b16 {%0,%1,%2,%3}, [%4];"
        : "=r"(d[0]), "=r"(d[1]), "=r"(d[2]), "=r"(d[3]) : "r"(a));
}
__device__ __forceinline__ void mma16816(float* d, const uint32_t* a, const uint32_t* b) {
    asm volatile("mma.sync.aligned.m16n8k16.row.col.f32.bf16.bf16.f32 "
        "{%0,%1,%2,%3}, {%4,%5,%6,%7}, {%8,%9}, {%0,%1,%2,%3};"
        : "+f"(d[0]), "+f"(d[1]), "+f"(d[2]), "+f"(d[3])
        : "r"(a[0]), "r"(a[1]), "r"(a[2]), "r"(a[3]), "r"(b[0]), "r"(b[1]));
}
__device__ __forceinline__ void split2(float x, float y, __nv_bfloat162& hi, __nv_bfloat162& lo) {
    __nv_bfloat16 hx = __float2bfloat16(x);
    __nv_bfloat16 hy = __float2bfloat16(y);
    hi = __nv_bfloat162(hx, hy);
    lo = __nv_bfloat162(__float2bfloat16(x - __bfloat162float(hx)),
                        __float2bfloat16(y - __bfloat162float(hy)));
}

// ------------------------- weight conversion ---------------------------------
// For each layer l < Ls: Bq_l (2K, ldB) = [Bh ; Bl] from W_l (K, Nw) row-major.
__global__ void convB_kernel(const float* __restrict__ W, __nv_bfloat16* __restrict__ Bq,
                             int K, int Nw, int ldB, int Ls, int wstride, long dstride,
                             int ncol_off) {
    int idx = blockIdx.x * blockDim.x + threadIdx.x;
    int per = K*Nw;
    if (idx >= per*Ls) return;
    int l = idx / per, r = idx - l*per;
    int k = r / Nw, n = r - k*Nw;
    float a = W[(size_t)l*wstride + r];
    __nv_bfloat16 h = __float2bfloat16(a);
    __nv_bfloat16 lo = __float2bfloat16(a - __bfloat162float(h));
    __nv_bfloat16* dst = Bq + (size_t)l*dstride + ncol_off;
    dst[(size_t)k*ldB + n]       = h;
    dst[(size_t)(K + k)*ldB + n] = lo;
}

// ------------------------- mma.sync GEMM -------------------------------------
// C(M,N) = A(M,K) @ B(K,N): 3 passes AhBh + AhBl + AlBh.
// A (M,2K) m-major split; B (2K,N) k-major split.  M%128==0, N%128==0, K%64==0.
// Outputs: GF_F32 -> C fp32 (ld N); GF_SPLIT -> Csp (M,2N) split bf16.
__global__ void __launch_bounds__(256, 2)
gemm3_kernel(const __nv_bfloat16* __restrict__ A, const __nv_bfloat16* __restrict__ B,
             float* __restrict__ C, __nv_bfloat16* __restrict__ Csp,
             int M, int N, int K, int flags) {
    extern __shared__ __align__(1024) char smem[];   // GSTG x (A 16KB + B 16KB)
    int tid = threadIdx.x;
    int lane = tid & 31, wid = tid >> 5;
    int warp_m = wid & 3, warp_n = wid >> 2;
    int mBase = blockIdx.y * 128, nBase = blockIdx.x * 128;
    int ldA = 2*K, ldB = N;
    int KTp = K >> 6, KT = 3*KTp;
    uint32_t sbase = smem_u32(smem);

    // A stage: 128 rows x 128B (64 bf16); B stage: 64 k-rows x 256B (128 bf16)
    #define LOAD_STAGE(g, s) do { \
        int p_ = (g)/KTp, kt_ = (g) - p_*KTp; \
        int ka_ = ((p_==2)?K:0) + (kt_<<6); \
        int kb_ = ((p_==1)?K:0) + (kt_<<6); \
        uint32_t sa_ = sbase + (s)*STGB; \
        uint32_t sb_ = sa_ + 16384; \
        const __nv_bfloat16* Ag_ = A + (size_t)mBase*ldA + ka_; \
        const __nv_bfloat16* Bg_ = B + (size_t)kb_*ldB + nBase; \
        _Pragma("unroll") \
        for (int i_ = 0; i_ < 4; i_++) { \
            int id_ = tid + i_*256; int r_ = id_ >> 3, c_ = id_ & 7; \
            cp_async16(sa_ + r_*128 + ((c_ ^ (r_&7)) << 4), \
                       Ag_ + (size_t)r_*ldA + c_*8); \
        } \
        _Pragma("unroll") \
        for (int i_ = 0; i_ < 4; i_++) { \
            int id_ = tid + i_*256; int r_ = id_ >> 4, c_ = id_ & 15; \
            cp_async16(sb_ + r_*256 + ((c_ ^ (r_&7)) << 4), \
                       Bg_ + (size_t)r_*ldB + c_*8); \
        } \
    } while (0)

    LOAD_STAGE(0, 0); cp_commit();
    LOAD_STAGE(1, 1); cp_commit();

    float acc[2][8][4];
    #pragma unroll
    for (int mi = 0; mi < 2; mi++)
        #pragma unroll
        for (int ni = 0; ni < 8; ni++)
            #pragma unroll
            for (int j = 0; j < 4; j++) acc[mi][ni][j] = 0.0f;

    for (int g = 0; g < KT; g++) {
        cp_wait1();
        __syncthreads();
        int cs = g % GSTG;                      // stage consumed this iteration
        uint32_t sa = sbase + cs*STGB;
        uint32_t sb = sa + 16384;
        #pragma unroll
        for (int kh = 0; kh < 4; kh++) {
            uint32_t af[2][4];
            #pragma unroll
            for (int mi = 0; mi < 2; mi++) {
                int r = warp_m*32 + mi*16 + (lane & 15);
                int c = kh*2 + (lane >> 4);
                ldsm4(af[mi], sa + r*128 + ((c ^ (r&7)) << 4));
            }
            uint32_t bq[4][4];
            #pragma unroll
            for (int ni2 = 0; ni2 < 4; ni2++) {
                int r = kh*16 + (lane & 15);
                int c = warp_n*8 + ni2*2 + (lane >> 4);
                ldsm4t(bq[ni2], sb + r*256 + ((c ^ (r&7)) << 4));
            }
            #pragma unroll
            for (int mi = 0; mi < 2; mi++)
                #pragma unroll
                for (int ni2 = 0; ni2 < 4; ni2++) {
                    mma16816(acc[mi][2*ni2],   af[mi], &bq[ni2][0]);
                    mma16816(acc[mi][2*ni2+1], af[mi], &bq[ni2][2]);
                }
        }
        // prefetch tile g+2 into stage (g+2)%3 == (g-1)%3 — fully consumed at
        // iter g-1; the top-of-loop __syncthreads of THIS iteration proved all
        // warps finished reading it.
        if (g + 2 < KT) LOAD_STAGE(g + 2, (g + 2) % GSTG);
        cp_commit();
    }

    // epilogue
    int relu = flags & GF_RELU;
    #pragma unroll
    for (int mi = 0; mi < 2; mi++) {
        int r0 = mBase + warp_m*32 + mi*16 + (lane >> 2);
        #pragma unroll
        for (int ni = 0; ni < 8; ni++) {
            int col = nBase + warp_n*64 + ni*8 + (lane & 3)*2;
            float2 v0 = make_float2(acc[mi][ni][0], acc[mi][ni][1]);
            float2 v1 = make_float2(acc[mi][ni][2], acc[mi][ni][3]);
            if (relu) {
                v0.x = fmaxf(v0.x, 0.f); v0.y = fmaxf(v0.y, 0.f);
                v1.x = fmaxf(v1.x, 0.f); v1.y = fmaxf(v1.y, 0.f);
            }
            if (flags & GF_F32) {
                *(float2*)(C + (size_t)r0*N + col)     = v0;
                *(float2*)(C + (size_t)(r0+8)*N + col) = v1;
            }
            if (flags & GF_SPLIT) {
                __nv_bfloat162 hi, lo;
                split2(v0.x, v0.y, hi, lo);
                *(__nv_bfloat162*)(Csp + (size_t)r0*2*N + col)     = hi;
                *(__nv_bfloat162*)(Csp + (size_t)r0*2*N + N + col) = lo;
                split2(v1.x, v1.y, hi, lo);
                *(__nv_bfloat162*)(Csp + (size_t)(r0+8)*2*N + col)     = hi;
                *(__nv_bfloat162*)(Csp + (size_t)(r0+8)*2*N + N + col) = lo;
            }
        }
    }
    #undef LOAD_STAGE
}

// ------------------------- helpers -----------------------------------------
__device__ __forceinline__ float n2n(float v) {
    if (isnan(v)) return 0.0f;
    if (isinf(v)) return v > 0.0f ? 3.4028235e38f : -3.4028235e38f;
    return v;
}
__device__ __forceinline__ void splitw(__nv_bfloat16* sp, size_t hi_idx, size_t lo_idx, float v) {
    __nv_bfloat16 h = __float2bfloat16(v);
    sp[hi_idx] = h;
    sp[lo_idx] = __float2bfloat16(v - __bfloat162float(h));
}

// ------------------------- feature kernel -----------------------------------
__global__ void feat_kernel(const float* __restrict__ x, const float* __restrict__ nb,
                            float* __restrict__ xf, float* __restrict__ nf,
                            unsigned char* __restrict__ mask) {
    int idx = blockIdx.x * blockDim.x + threadIdx.x;
    if (idx >= T_*N_*NN_) return;
    int nn = idx & (NN_-1);
    int rem = idx >> 5;
    int n  = rem & (N_-1);
    int t  = rem >> 6;
    const float* xr = x + ((size_t)t*N_ + n)*6;
    float px = xr[0], py = xr[1];
    float vx, vy;
    if (t == 0) {
        const float* x1 = x + ((size_t)1*N_ + n)*6;
        vx = x1[2]; vy = x1[3];
    } else {
        const float* xp = x + ((size_t)(t-1)*N_ + n)*6;
        vx = px - xp[0]; vy = py - xp[1];
    }
    const float* nr = nb + (((size_t)t*N_ + n)*NN_ + nn)*4;
    float dpx = nr[0]-px, dpy = nr[1]-py;
    float dvx = nr[2]-vx, dvy = nr[3]-vy;
    float dist = sqrtf(dpx*dpx + dpy*dpy);
    mask[(n*NN_ + nn)*T_ + t] = (dist <= 2.0f) ? 1 : 0;
    float nv = sqrtf(vx*vx + vy*vy);
    float bearing = (dpx*vx + dpy*vy) / (dist*nv);
    if (isnan(bearing)) bearing = 0.0f;
    float ndv = sqrtf(dvx*dvx + dvy*dvy);
    float tau = -(dpx*dvx + dpy*dvy) / ndv;
    if (isnan(tau)) tau = 0.0f;
    tau = fminf(fmaxf(tau, 0.0f), 7.0f);
    float mxx = dpx + tau*dvx, myy = dpy + tau*dvy;
    float mpd = sqrtf(mxx*mxx + myy*myy);
    float* o = nf + (size_t)idx*3;
    o[0] = n2n(dist); o[1] = n2n(bearing); o[2] = n2n(mpd);
    if (nn == 0) {
        float vel = sqrtf(xr[2]*xr[2] + xr[3]*xr[3]);
        float ang = atanf(xr[5]/xr[4]);
        float* xo = xf + ((size_t)t*N_ + n)*4;
        xo[0] = n2n(xr[0]); xo[1] = n2n(xr[1]); xo[2] = n2n(vel); xo[3] = n2n(ang);
    }
}

// ------------------------- positional encoding -------------------------------
__global__ void pe_kernel(float* __restrict__ pe) {
    int i = blockIdx.x * blockDim.x + threadIdx.x;
    if (i >= T_*D_) return;
    int t = i >> 9, d = i & (D_-1);
    double expo = (double)(d & ~1) / (double)D_;
    float div = (float)exp(expo * 9.210340371976184);
    float arg = (float)t * div;
    pe[i] = (d & 1) ? (float)cos((double)arg) : (float)sin((double)arg);
}

// ------------------------- embeddings ----------------------------------------
__global__ void xemb_kernel(const float* __restrict__ xf, const float* __restrict__ Wx,
                            const float* __restrict__ bx, const float* __restrict__ pe,
                            float* __restrict__ xe) {
    int i = blockIdx.x * blockDim.x + threadIdx.x;
    if (i >= NTOKS*D_) return;
    int d = i & (D_-1);
    int tok = i >> 9;
    int t = tok >> 6, n = tok & (N_-1);
    const float* f = xf + (size_t)tok*4;
    float acc = bx[d] + pe[t*D_ + d];
    #pragma unroll
    for (int k = 0; k < 4; k++) acc = fmaf(f[k], Wx[k*D_ + d], acc);
    xe[((size_t)(n*T_ + t))*D_ + d] = acc;
}

// writes ne fp32 (residual use) + split bf16 (GEMM A use)
__global__ void nemb_kernel(const float* __restrict__ nf, const float* __restrict__ Wn,
                            const float* __restrict__ bn, const float* __restrict__ pe,
                            float* __restrict__ ne, __nv_bfloat16* __restrict__ sp) {
    size_t i = (size_t)blockIdx.x * blockDim.x + threadIdx.x;
    if (i >= (size_t)NTOKB*D_) return;
    int d = (int)(i & (D_-1));
    int tok = (int)(i >> 9);
    int nn = tok & (NN_-1);
    int rem = tok >> 5;
    int n = rem & (N_-1);
    int t = rem >> 6;
    const float* f = nf + (size_t)tok*3;
    float acc = bn[d] + pe[t*D_ + d];
    acc = fmaf(f[0], Wn[d], acc);
    acc = fmaf(f[1], Wn[D_ + d], acc);
    acc = fmaf(f[2], Wn[2*D_ + d], acc);
    size_t row = (size_t)(n*NN_ + nn)*T_ + t;
    ne[row*D_ + d] = acc;
    splitw(sp, row*2*D_ + d, row*2*D_ + D_ + d, acc);
}

// ------------------------- neighbor attention --------------------------------
__global__ void attn_kernel(const float* __restrict__ QKV, const unsigned char* __restrict__ mask,
                            __nv_bfloat16* __restrict__ spCtx, float* __restrict__ attn_out) {
    int b = blockIdx.x;
    int h = b & (H_-1);
    int pair = b >> 3;
    int tid = threadIdx.x;
    __shared__ float q[16*68], k[16*68], v[16*68];
    __shared__ float at[16*17];
    size_t base = (size_t)pair*T_*1536 + h*DK_;
    for (int i = tid; i < 16*64; i += 256) {
        int t = i >> 6, d = i & 63;
        q[t*68+d] = QKV[base + (size_t)t*1536 + d];
        k[t*68+d] = QKV[base + (size_t)t*1536 + 512 + d];
        v[t*68+d] = QKV[base + (size_t)t*1536 + 1024 + d];
    }
    __syncthreads();
    int qt = tid >> 4, kt = tid & 15;
    float s = 0.0f;
    #pragma unroll
    for (int d = 0; d < 64; d++) s = fmaf(q[qt*68+d], k[kt*68+d], s);
    s *= 0.125f;
    if (!mask[pair*T_ + qt]) s = -1e9f;
    float mx = s;
    #pragma unroll
    for (int o = 8; o; o >>= 1) mx = fmaxf(mx, __shfl_xor_sync(0xffffffffu, mx, o));
    float e = expf(s - mx);
    float sum = e;
    #pragma unroll
    for (int o = 8; o; o >>= 1) sum += __shfl_xor_sync(0xffffffffu, sum, o);
    float a = e / sum;
    at[qt*17 + kt] = a;
    attn_out[(size_t)b*256 + qt*16 + kt] = a;
    __syncthreads();
    for (int i = tid; i < 16*64; i += 256) {
        int t = i >> 6, d = i & 63;
        float acc = 0.0f;
        #pragma unroll
        for (int kk = 0; kk < 16; kk++) acc = fmaf(at[t*17+kk], v[kk*68+d], acc);
        size_t row = (size_t)pair*T_ + t;
        splitw(spCtx, row*1024 + h*DK_ + d, row*1024 + 512 + h*DK_ + d, acc);
    }
}

__global__ void attmean_kernel(const float* __restrict__ attn, float* __restrict__ attint) {
    int i = blockIdx.x * blockDim.x + threadIdx.x;
    if (i >= N_*H_*256) return;
    int qk = i & 255;
    int h  = (i >> 8) & (H_-1);
    int n  = i >> 11;
    float s = 0.0f;
    #pragma unroll 4
    for (int nn = 0; nn < NN_; nn++)
        s += attn[(((size_t)(n*NN_ + nn)*H_ + h)*256) + qk];
    attint[i] = s * (1.0f/32.0f);
}

// ------------------------- add + layernorm (optional split out) --------------
__global__ void add_ln_kernel(const float* __restrict__ X, const float* __restrict__ R,
                              const float* __restrict__ g, const float* __restrict__ b,
                              float* __restrict__ out, __nv_bfloat16* __restrict__ sp) {
    int row = blockIdx.x, tid = threadIdx.x;
    size_t off = (size_t)row*D_;
    float x0 = X[off+tid]     + R[off+tid];
    float x1 = X[off+256+tid] + R[off+256+tid];
    __shared__ float red[8], red2[8];
    float s = x0 + x1;
    #pragma unroll
    for (int o = 16; o; o >>= 1) s += __shfl_xor_sync(0xffffffffu, s, o);
    if ((tid & 31) == 0) red[tid >> 5] = s;
    __syncthreads();
    float tot = 0.0f;
    #pragma unroll
    for (int i = 0; i < 8; i++) tot += red[i];
    float m = tot * (1.0f/512.0f);
    float d0 = x0 - m, d1 = x1 - m;
    float vs = d0*d0 + d1*d1;
    #pragma unroll
    for (int o = 16; o; o >>= 1) vs += __shfl_xor_sync(0xffffffffu, vs, o);
    if ((tid & 31) == 0) red2[tid >> 5] = vs;
    __syncthreads();
    float vtot = 0.0f;
    #pragma unroll
    for (int i = 0; i < 8; i++) vtot += red2[i];
    float inv = 1.0f / sqrtf(vtot * (1.0f/512.0f) + 1e-5f);
    float o0 = d0*inv*g[tid]     + b[tid];
    float o1 = d1*inv*g[tid+256] + b[tid+256];
    out[off+tid]     = o0;
    out[off+256+tid] = o1;
    if (sp) {
        size_t sro = (size_t)row*1024;
        splitw(sp, sro + tid,       sro + 512 + tid,       o0);
        splitw(sp, sro + 256 + tid, sro + 768 + tid,       o1);
    }
}

// ------------------------- self attention ------------------------------------
__global__ void attself_kernel(const float* __restrict__ xe, float* __restrict__ attself) {
    int n = blockIdx.x;
    int tid = threadIdx.x;
    __shared__ float xs[16*516];
    for (int i = tid; i < 16*D_; i += 256) {
        int t = i >> 9, d = i & (D_-1);
        xs[t*516 + d] = xe[((size_t)(n*T_ + t))*D_ + d];
    }
    __syncthreads();
    int q = tid >> 4, k = tid & 15;
    float s = 0.0f;
    for (int d = 0; d < D_; d++) s = fmaf(xs[q*516+d], xs[k*516+d], s);
    s *= 0.04419417382415922f;
    float mx = s;
    #pragma unroll
    for (int o = 8; o; o >>= 1) mx = fmaxf(mx, __shfl_xor_sync(0xffffffffu, mx, o));
    float e = expf(s - mx);
    float sum = e;
    #pragma unroll
    for (int o = 8; o; o >>= 1) sum += __shfl_xor_sync(0xffffffffu, sum, o);
    attself[(size_t)n*256 + q*16 + k] = e / sum;
}

// ------------------------- si (split out, row stride 2*H*D) ------------------
__global__ void si_kernel(const float* __restrict__ xe, const float* __restrict__ attself,
                          const float* __restrict__ attint, const float* __restrict__ att_factor,
                          __nv_bfloat16* __restrict__ spSi) {
    int n = blockIdx.x >> 4;
    int q = blockIdx.x & 15;
    int tid = threadIdx.x;
    __shared__ float xs[16*512];
    __shared__ float arow[H_*16];
    float factor = att_factor[0];
    for (int i = tid; i < 16*D_; i += 512) xs[i] = xe[(size_t)n*T_*D_ + i];
    if (tid < H_*16) {
        int h = tid >> 4, t = tid & 15;
        arow[tid] = attself[(size_t)n*256 + q*16 + t]
                  + factor * attint[((n*H_ + h)*16 + q)*16 + t];
    }
    __syncthreads();
    int d = tid;
    size_t row = (size_t)(n*T_ + q);
    #pragma unroll
    for (int h = 0; h < H_; h++) {
        float acc = 0.0f;
        #pragma unroll
        for (int t = 0; t < 16; t++) acc = fmaf(arow[h*16+t], xs[t*512 + d], acc);
        splitw(spSi, row*8192 + h*D_ + d, row*8192 + 4096 + h*D_ + d, acc);
    }
}

// ------------------------- prediction head -----------------------------------
__global__ void pred_kernel(const float* __restrict__ xe, const float* __restrict__ Wp,
                            const float* __restrict__ bp, float* __restrict__ out) {
    int idx = blockIdx.x * blockDim.x + threadIdx.x;
    if (idx >= N_*T_*2) return;
    int c = idx & 1;
    int t = (idx >> 1) & 15;
    int n = idx >> 5;
    float acc = bp[c];
    const float* xr = xe + ((size_t)(n*T_ + t))*D_;
    for (int d = 0; d < D_; d++) acc = fmaf(xr[d], Wp[d*2 + c], acc);
    for (int p = 0; p < 20; p++)
        out[(((size_t)p*T_ + t)*N_ + n)*2 + c] = acc;
}

// ---------------------------------------------------------------------------
static inline void convB(const float* W, __nv_bfloat16* Bq, int K, int Nw, int ldB,
                         int Ls, int wstride, long dstride, int ncol_off) {
    convB_kernel<<<((long)K*Nw*Ls+255)/256, 256>>>(W, Bq, K, Nw, ldB, Ls, wstride,
                                                   dstride, ncol_off);
}
static inline void gemm3(const __nv_bfloat16* A, const __nv_bfloat16* Bq,
                         float* C, __nv_bfloat16* Csp,
                         int M, int N, int K, int flags) {
    dim3 grid(N/128, M/128);
    gemm3_kernel<<<grid, 256, GSMEM_BYTES>>>(A, Bq, C, Csp, M, N, K, flags);
}

extern "C" void kernel_launch(void* const* d_in, const int* in_sizes, int n_in,
                              void* d_out, int out_size) {
    const float* x        = (const float*)d_in[0];
    const float* neighbor = (const float*)d_in[1];
    const float* att_fac  = (const float*)d_in[2];
    const float* Wx       = (const float*)d_in[3];
    const float* bx       = (const float*)d_in[4];
    const float* Wn       = (const float*)d_in[5];
    const float* bn       = (const float*)d_in[6];
    const float* Wpred    = (const float*)d_in[7];
    const float* bpred    = (const float*)d_in[8];
    const float* WQ       = (const float*)d_in[9];
    const float* WK       = (const float*)d_in[10];
    const float* WV       = (const float*)d_in[11];
    const float* Wfc      = (const float*)d_in[12];
    const float* mha_g    = (const float*)d_in[13];
    const float* mha_b    = (const float*)d_in[14];
    const float* WSI      = (const float*)d_in[15];
    const float* ffs_w1   = (const float*)d_in[16];
    const float* ffs_w2   = (const float*)d_in[17];
    const float* ffs_g    = (const float*)d_in[18];
    const float* ffs_b    = (const float*)d_in[19];
    const float* ffi_w1   = (const float*)d_in[20];
    const float* ffi_w2   = (const float*)d_in[21];
    const float* ffi_g    = (const float*)d_in[22];
    const float* ffi_b    = (const float*)d_in[23];
    float* out = (float*)d_out;

    static float *pxf=0,*pnf=0,*ppe=0,*pxe=0,*pne=0,*pqkv=0,
                 *ptmpM=0,*pres=0,*pattn=0,*pattint=0,*pattself=0,
                 *pxnew=0,*ptmpS=0;
    static __nv_bfloat16 *pBw=0,*spNe=0,*spCtx=0,*spRes=0,*spHidM=0,
                         *spSi=0,*spXnew=0,*spHidS=0;
    static unsigned char* pmask=0;
    if (!pxf) {
        cudaGetSymbolAddress((void**)&pxf, g_xf);
        cudaGetSymbolAddress((void**)&pnf, g_nf);
        cudaGetSymbolAddress((void**)&pmask, g_mask);
        cudaGetSymbolAddress((void**)&ppe, g_pe);
        cudaGetSymbolAddress((void**)&pxe, g_xe);
        cudaGetSymbolAddress((void**)&pne, g_ne);
        cudaGetSymbolAddress((void**)&pqkv, g_QKV);
        cudaGetSymbolAddress((void**)&ptmpM, g_tmpM);
        cudaGetSymbolAddress((void**)&pres, g_res);
        cudaGetSymbolAddress((void**)&pattn, g_attn);
        cudaGetSymbolAddress((void**)&pattint, g_attint);
        cudaGetSymbolAddress((void**)&pattself, g_attself);
        cudaGetSymbolAddress((void**)&pxnew, g_xnew);
        cudaGetSymbolAddress((void**)&ptmpS, g_tmpS);
        cudaGetSymbolAddress((void**)&pBw, g_Bw);
        cudaGetSymbolAddress((void**)&spNe, g_spNe);
        cudaGetSymbolAddress((void**)&spCtx, g_spCtx);
        cudaGetSymbolAddress((void**)&spRes, g_spRes);
        cudaGetSymbolAddress((void**)&spHidM, g_spHidM);
        cudaGetSymbolAddress((void**)&spSi, g_spSi);
        cudaGetSymbolAddress((void**)&spXnew, g_spXnew);
        cudaGetSymbolAddress((void**)&spHidS, g_spHidS);
        cudaFuncSetAttribute(gemm3_kernel, cudaFuncAttributeMaxDynamicSharedMemorySize,
                             GSMEM_BYTES);
    }

    // convert all weights for both layers up front (batched over L)
    convB(WQ, pBw + WOFF_QKV,        D_, D_, 1536, L_, D_*D_, WSZ_LAYER, 0);
    convB(WK, pBw + WOFF_QKV,        D_, D_, 1536, L_, D_*D_, WSZ_LAYER, 512);
    convB(WV, pBw + WOFF_QKV,        D_, D_, 1536, L_, D_*D_, WSZ_LAYER, 1024);
    convB(Wfc, pBw + WOFF_FC,        D_, D_, D_,   L_, D_*D_, WSZ_LAYER, 0);
    convB(WSI, pBw + WOFF_SI,    H_*D_, D_, D_,    L_, H_*D_*D_, WSZ_LAYER, 0);
    convB(ffs_w1, pBw + WOFF_FS1,    D_, DFF_, DFF_, L_, D_*DFF_, WSZ_LAYER, 0);
    convB(ffs_w2, pBw + WOFF_FS2,  DFF_, D_, D_,   L_, DFF_*D_, WSZ_LAYER, 0);
    convB(ffi_w1, pBw + WOFF_FI1,    D_, DFF_, DFF_, L_, D_*DFF_, WSZ_LAYER, 0);
    convB(ffi_w2, pBw + WOFF_FI2,  DFF_, D_, D_,   L_, DFF_*D_, WSZ_LAYER, 0);

    feat_kernel<<<(T_*N_*NN_+255)/256, 256>>>(x, neighbor, pxf, pnf, pmask);
    pe_kernel<<<(T_*D_+255)/256, 256>>>(ppe);
    xemb_kernel<<<(NTOKS*D_+255)/256, 256>>>(pxf, Wx, bx, ppe, pxe);
    nemb_kernel<<<(int)(((size_t)NTOKB*D_+255)/256), 256>>>(pnf, Wn, bn, ppe, pne, spNe);

    for (int l = 0; l < L_; l++) {
        __nv_bfloat16* Bl = pBw + (size_t)l*WSZ_LAYER;

        gemm3(spNe, Bl + WOFF_QKV, pqkv, 0, NTOKB, 3*D_, D_, GF_F32);

        attn_kernel<<<NPAIR*H_, 256>>>(pqkv, pmask, spCtx, pattn);
        attmean_kernel<<<(N_*H_*256+255)/256, 256>>>(pattn, pattint);

        gemm3(spCtx, Bl + WOFF_FC, ptmpM, 0, NTOKB, D_, D_, GF_F32);
        add_ln_kernel<<<NTOKB, 256>>>(ptmpM, pne, mha_g + l*D_, mha_b + l*D_, pres, spRes);

        attself_kernel<<<N_, 256>>>(pxe, pattself);
        si_kernel<<<NTOKS, 512>>>(pxe, pattself, pattint, att_fac, spSi);

        gemm3(spSi, Bl + WOFF_SI, pxnew, spXnew, NTOKS, D_, H_*D_, GF_F32 | GF_SPLIT);

        gemm3(spXnew, Bl + WOFF_FS1, 0, spHidS, NTOKS, DFF_, D_, GF_RELU | GF_SPLIT);
        gemm3(spHidS, Bl + WOFF_FS2, ptmpS, 0, NTOKS, D_, DFF_, GF_F32);
        add_ln_kernel<<<NTOKS, 256>>>(ptmpS, pxnew, ffs_g + l*D_, ffs_b + l*D_, pxe, 0);

        gemm3(spRes, Bl + WOFF_FI1, 0, spHidM, NTOKB, DFF_, D_, GF_RELU | GF_SPLIT);
        gemm3(spHidM, Bl + WOFF_FI2, ptmpM, 0, NTOKB, D_, DFF_, GF_F32);
        add_ln_kernel<<<NTOKB, 256>>>(ptmpM, pres, ffi_g + l*D_, ffi_b + l*D_, pne,
                                      (l+1 < L_) ? spNe : 0);
    }

    pred_kernel<<<(N_*T_*2+255)/256, 256>>>(pxe, Wpred, bpred, out);
}

// round 15
// speedup vs baseline: 3.1533x; 1.1317x over previous
#include <cuda_runtime.h>
#include <cuda_bf16.h>
#include <math.h>
#include <float.h>
#include <stdint.h>

// ---------------------------------------------------------------------------
// SocialTrans: T=16, N=64, NN=32, D=512, H=8, DK=64, DFF=2048, L=2
// GEMMs via mma.sync bf16 split-precision (AhBh+AhBl+AlBh, fp32 accum).
// k64 stages, 3-stage cp.async pipeline, 2 CTAs/SM, pre-converted weights.
// Self-branch overlapped with neighbor-branch on a second captured stream.
// ---------------------------------------------------------------------------
#define T_ 16
#define N_ 64
#define NN_ 32
#define D_ 512
#define H_ 8
#define DK_ 64
#define DFF_ 2048
#define L_ 2
#define NPAIR (N_*NN_)          // 2048
#define NTOKB (NPAIR*T_)        // 32768  neighbor tokens
#define NTOKS (N_*T_)           // 1024   self tokens

#define GF_RELU 1
#define GF_SPLIT 2
#define GF_F32 4

#define GSTG 3
#define STGB 32768              // stage bytes: A 16KB + B 16KB
#define GSMEM_BYTES (GSTG*STGB)

// weight arena offsets (bf16 elements, per layer)
#define WOFF_QKV 0
#define WSZ_QKV  (1024*1536)
#define WOFF_FC  (WOFF_QKV + WSZ_QKV)
#define WSZ_FC   (1024*512)
#define WOFF_SI  (WOFF_FC + WSZ_FC)
#define WSZ_SI   (8192*512)
#define WOFF_FS1 (WOFF_SI + WSZ_SI)
#define WSZ_FS1  (1024*2048)
#define WOFF_FS2 (WOFF_FS1 + WSZ_FS1)
#define WSZ_FS2  (4096*512)
#define WOFF_FI1 (WOFF_FS2 + WSZ_FS2)
#define WSZ_FI1  (1024*2048)
#define WOFF_FI2 (WOFF_FI1 + WSZ_FI1)
#define WSZ_FI2  (4096*512)
#define WSZ_LAYER (WOFF_FI2 + WSZ_FI2)

// ------------------------- device scratch (static, no allocs) --------------
__device__ float g_xf  [T_*N_*4];
__device__ float g_nf  [T_*N_*NN_*3];
__device__ unsigned char g_mask[NPAIR*T_];
__device__ float g_pe  [T_*D_];
__device__ float g_xe  [NTOKS*D_];
__device__ float g_ne  [NTOKB*D_];
__device__ float g_QKV [NTOKB*3*D_];
__device__ float g_tmpM[NTOKB*D_];
__device__ float g_res [NTOKB*D_];
__device__ float g_attn[NPAIR*H_*T_*T_];
__device__ float g_attint[N_*H_*T_*T_];
__device__ float g_attself[N_*T_*T_];
__device__ float g_xnew[NTOKS*D_];
__device__ float g_tmpS[NTOKS*D_];
// split (hi|lo) bf16 buffers, row stride = 2K
__device__ __nv_bfloat16 g_spNe  [NTOKB*2*D_];
__device__ __nv_bfloat16 g_spCtx [NTOKB*2*D_];
__device__ __nv_bfloat16 g_spRes [NTOKB*2*D_];
__device__ __nv_bfloat16 g_spHidM[(size_t)NTOKB*2*DFF_];
__device__ __nv_bfloat16 g_spSi  [NTOKS*2*H_*D_];
__device__ __nv_bfloat16 g_spXnew[NTOKS*2*D_];
__device__ __nv_bfloat16 g_spHidS[NTOKS*2*DFF_];
__device__ __nv_bfloat16 g_Bw[(size_t)L_*WSZ_LAYER];   // pre-converted weights

// ------------------------- PTX helpers --------------------------------------
__device__ __forceinline__ uint32_t smem_u32(const void* p) {
    uint32_t a;
    asm("{ .reg .u64 t; cvta.to.shared.u64 t, %1; cvt.u32.u64 %0, t; }" : "=r"(a) : "l"(p));
    return a;
}
__device__ __forceinline__ void cp_async16(uint32_t saddr, const void* gaddr) {
    asm volatile("cp.async.cg.shared.global [%0], [%1], 16;" :: "r"(saddr), "l"(gaddr));
}
__device__ __forceinline__ void cp_commit() { asm volatile("cp.async.commit_group;" ::: "memory"); }
__device__ __forceinline__ void cp_wait1()  { asm volatile("cp.async.wait_group 1;" ::: "memory"); }

__device__ __forceinline__ void ldsm4(uint32_t* d, uint32_t a) {
    asm volatile("ldmatrix.sync.aligned.m8n8.x4.shared.b16 {%0,%1,%2,%3}, [%4];"
        : "=r"(d[0]), "=r"(d[1]), "=r"(d[2]), "=r"(d[3]) : "r"(a));
}
__device__ __forceinline__ void ldsm4t(uint32_t* d, uint32_t a) {
    asm volatile("ldmatrix.sync.aligned.m8n8.x4.trans.shared.b16 {%0,%1,%2,%3}, [%4];"
        : "=r"(d[0]), "=r"(d[1]), "=r"(d[2]), "=r"(d[3]) : "r"(a));
}
__device__ __forceinline__ void mma16816(float* d, const uint32_t* a, const uint32_t* b) {
    asm volatile("mma.sync.aligned.m16n8k16.row.col.f32.bf16.bf16.f32 "
        "{%0,%1,%2,%3}, {%4,%5,%6,%7}, {%8,%9}, {%0,%1,%2,%3};"
        : "+f"(d[0]), "+f"(d[1]), "+f"(d[2]), "+f"(d[3])
        : "r"(a[0]), "r"(a[1]), "r"(a[2]), "r"(a[3]), "r"(b[0]), "r"(b[1]));
}
__device__ __forceinline__ void split2(float x, float y, __nv_bfloat162& hi, __nv_bfloat162& lo) {
    __nv_bfloat16 hx = __float2bfloat16(x);
    __nv_bfloat16 hy = __float2bfloat16(y);
    hi = __nv_bfloat162(hx, hy);
    lo = __nv_bfloat162(__float2bfloat16(x - __bfloat162float(hx)),
                        __float2bfloat16(y - __bfloat162float(hy)));
}

// ------------------------- weight conversion ---------------------------------
__global__ void convB_kernel(const float* __restrict__ W, __nv_bfloat16* __restrict__ Bq,
                             int K, int Nw, int ldB, int Ls, int wstride, long dstride,
                             int ncol_off) {
    int idx = blockIdx.x * blockDim.x + threadIdx.x;
    int per = K*Nw;
    if (idx >= per*Ls) return;
    int l = idx / per, r = idx - l*per;
    int k = r / Nw, n = r - k*Nw;
    float a = W[(size_t)l*wstride + r];
    __nv_bfloat16 h = __float2bfloat16(a);
    __nv_bfloat16 lo = __float2bfloat16(a - __bfloat162float(h));
    __nv_bfloat16* dst = Bq + (size_t)l*dstride + ncol_off;
    dst[(size_t)k*ldB + n]       = h;
    dst[(size_t)(K + k)*ldB + n] = lo;
}

// ------------------------- mma.sync GEMM -------------------------------------
__global__ void __launch_bounds__(256, 2)
gemm3_kernel(const __nv_bfloat16* __restrict__ A, const __nv_bfloat16* __restrict__ B,
             float* __restrict__ C, __nv_bfloat16* __restrict__ Csp,
             int M, int N, int K, int flags) {
    extern __shared__ __align__(1024) char smem[];   // GSTG x (A 16KB + B 16KB)
    int tid = threadIdx.x;
    int lane = tid & 31, wid = tid >> 5;
    int warp_m = wid & 3, warp_n = wid >> 2;
    int mBase = blockIdx.y * 128, nBase = blockIdx.x * 128;
    int ldA = 2*K, ldB = N;
    int KTp = K >> 6, KT = 3*KTp;
    uint32_t sbase = smem_u32(smem);

    #define LOAD_STAGE(g, s) do { \
        int p_ = (g)/KTp, kt_ = (g) - p_*KTp; \
        int ka_ = ((p_==2)?K:0) + (kt_<<6); \
        int kb_ = ((p_==1)?K:0) + (kt_<<6); \
        uint32_t sa_ = sbase + (s)*STGB; \
        uint32_t sb_ = sa_ + 16384; \
        const __nv_bfloat16* Ag_ = A + (size_t)mBase*ldA + ka_; \
        const __nv_bfloat16* Bg_ = B + (size_t)kb_*ldB + nBase; \
        _Pragma("unroll") \
        for (int i_ = 0; i_ < 4; i_++) { \
            int id_ = tid + i_*256; int r_ = id_ >> 3, c_ = id_ & 7; \
            cp_async16(sa_ + r_*128 + ((c_ ^ (r_&7)) << 4), \
                       Ag_ + (size_t)r_*ldA + c_*8); \
        } \
        _Pragma("unroll") \
        for (int i_ = 0; i_ < 4; i_++) { \
            int id_ = tid + i_*256; int r_ = id_ >> 4, c_ = id_ & 15; \
            cp_async16(sb_ + r_*256 + ((c_ ^ (r_&7)) << 4), \
                       Bg_ + (size_t)r_*ldB + c_*8); \
        } \
    } while (0)

    LOAD_STAGE(0, 0); cp_commit();
    LOAD_STAGE(1, 1); cp_commit();

    float acc[2][8][4];
    #pragma unroll
    for (int mi = 0; mi < 2; mi++)
        #pragma unroll
        for (int ni = 0; ni < 8; ni++)
            #pragma unroll
            for (int j = 0; j < 4; j++) acc[mi][ni][j] = 0.0f;

    for (int g = 0; g < KT; g++) {
        cp_wait1();
        __syncthreads();
        int cs = g % GSTG;
        uint32_t sa = sbase + cs*STGB;
        uint32_t sb = sa + 16384;
        #pragma unroll
        for (int kh = 0; kh < 4; kh++) {
            uint32_t af[2][4];
            #pragma unroll
            for (int mi = 0; mi < 2; mi++) {
                int r = warp_m*32 + mi*16 + (lane & 15);
                int c = kh*2 + (lane >> 4);
                ldsm4(af[mi], sa + r*128 + ((c ^ (r&7)) << 4));
            }
            uint32_t bq[4][4];
            #pragma unroll
            for (int ni2 = 0; ni2 < 4; ni2++) {
                int r = kh*16 + (lane & 15);
                int c = warp_n*8 + ni2*2 + (lane >> 4);
                ldsm4t(bq[ni2], sb + r*256 + ((c ^ (r&7)) << 4));
            }
            #pragma unroll
            for (int mi = 0; mi < 2; mi++)
                #pragma unroll
                for (int ni2 = 0; ni2 < 4; ni2++) {
                    mma16816(acc[mi][2*ni2],   af[mi], &bq[ni2][0]);
                    mma16816(acc[mi][2*ni2+1], af[mi], &bq[ni2][2]);
                }
        }
        // prefetch into stage (g+2)%3 — consumed at iter g-1, safe per the
        // top-of-loop __syncthreads of this iteration.
        if (g + 2 < KT) LOAD_STAGE(g + 2, (g + 2) % GSTG);
        cp_commit();
    }

    int relu = flags & GF_RELU;
    #pragma unroll
    for (int mi = 0; mi < 2; mi++) {
        int r0 = mBase + warp_m*32 + mi*16 + (lane >> 2);
        #pragma unroll
        for (int ni = 0; ni < 8; ni++) {
            int col = nBase + warp_n*64 + ni*8 + (lane & 3)*2;
            float2 v0 = make_float2(acc[mi][ni][0], acc[mi][ni][1]);
            float2 v1 = make_float2(acc[mi][ni][2], acc[mi][ni][3]);
            if (relu) {
                v0.x = fmaxf(v0.x, 0.f); v0.y = fmaxf(v0.y, 0.f);
                v1.x = fmaxf(v1.x, 0.f); v1.y = fmaxf(v1.y, 0.f);
            }
            if (flags & GF_F32) {
                *(float2*)(C + (size_t)r0*N + col)     = v0;
                *(float2*)(C + (size_t)(r0+8)*N + col) = v1;
            }
            if (flags & GF_SPLIT) {
                __nv_bfloat162 hi, lo;
                split2(v0.x, v0.y, hi, lo);
                *(__nv_bfloat162*)(Csp + (size_t)r0*2*N + col)     = hi;
                *(__nv_bfloat162*)(Csp + (size_t)r0*2*N + N + col) = lo;
                split2(v1.x, v1.y, hi, lo);
                *(__nv_bfloat162*)(Csp + (size_t)(r0+8)*2*N + col)     = hi;
                *(__nv_bfloat162*)(Csp + (size_t)(r0+8)*2*N + N + col) = lo;
            }
        }
    }
    #undef LOAD_STAGE
}

// ------------------------- helpers -----------------------------------------
__device__ __forceinline__ float n2n(float v) {
    if (isnan(v)) return 0.0f;
    if (isinf(v)) return v > 0.0f ? 3.4028235e38f : -3.4028235e38f;
    return v;
}
__device__ __forceinline__ void splitw(__nv_bfloat16* sp, size_t hi_idx, size_t lo_idx, float v) {
    __nv_bfloat16 h = __float2bfloat16(v);
    sp[hi_idx] = h;
    sp[lo_idx] = __float2bfloat16(v - __bfloat162float(h));
}

// ------------------------- feature kernel -----------------------------------
__global__ void feat_kernel(const float* __restrict__ x, const float* __restrict__ nb,
                            float* __restrict__ xf, float* __restrict__ nf,
                            unsigned char* __restrict__ mask) {
    int idx = blockIdx.x * blockDim.x + threadIdx.x;
    if (idx >= T_*N_*NN_) return;
    int nn = idx & (NN_-1);
    int rem = idx >> 5;
    int n  = rem & (N_-1);
    int t  = rem >> 6;
    const float* xr = x + ((size_t)t*N_ + n)*6;
    float px = xr[0], py = xr[1];
    float vx, vy;
    if (t == 0) {
        const float* x1 = x + ((size_t)1*N_ + n)*6;
        vx = x1[2]; vy = x1[3];
    } else {
        const float* xp = x + ((size_t)(t-1)*N_ + n)*6;
        vx = px - xp[0]; vy = py - xp[1];
    }
    const float* nr = nb + (((size_t)t*N_ + n)*NN_ + nn)*4;
    float dpx = nr[0]-px, dpy = nr[1]-py;
    float dvx = nr[2]-vx, dvy = nr[3]-vy;
    float dist = sqrtf(dpx*dpx + dpy*dpy);
    mask[(n*NN_ + nn)*T_ + t] = (dist <= 2.0f) ? 1 : 0;
    float nv = sqrtf(vx*vx + vy*vy);
    float bearing = (dpx*vx + dpy*vy) / (dist*nv);
    if (isnan(bearing)) bearing = 0.0f;
    float ndv = sqrtf(dvx*dvx + dvy*dvy);
    float tau = -(dpx*dvx + dpy*dvy) / ndv;
    if (isnan(tau)) tau = 0.0f;
    tau = fminf(fmaxf(tau, 0.0f), 7.0f);
    float mxx = dpx + tau*dvx, myy = dpy + tau*dvy;
    float mpd = sqrtf(mxx*mxx + myy*myy);
    float* o = nf + (size_t)idx*3;
    o[0] = n2n(dist); o[1] = n2n(bearing); o[2] = n2n(mpd);
    if (nn == 0) {
        float vel = sqrtf(xr[2]*xr[2] + xr[3]*xr[3]);
        float ang = atanf(xr[5]/xr[4]);
        float* xo = xf + ((size_t)t*N_ + n)*4;
        xo[0] = n2n(xr[0]); xo[1] = n2n(xr[1]); xo[2] = n2n(vel); xo[3] = n2n(ang);
    }
}

// ------------------------- positional encoding -------------------------------
__global__ void pe_kernel(float* __restrict__ pe) {
    int i = blockIdx.x * blockDim.x + threadIdx.x;
    if (i >= T_*D_) return;
    int t = i >> 9, d = i & (D_-1);
    double expo = (double)(d & ~1) / (double)D_;
    float div = (float)exp(expo * 9.210340371976184);
    float arg = (float)t * div;
    pe[i] = (d & 1) ? (float)cos((double)arg) : (float)sin((double)arg);
}

// ------------------------- embeddings ----------------------------------------
__global__ void xemb_kernel(const float* __restrict__ xf, const float* __restrict__ Wx,
                            const float* __restrict__ bx, const float* __restrict__ pe,
                            float* __restrict__ xe) {
    int i = blockIdx.x * blockDim.x + threadIdx.x;
    if (i >= NTOKS*D_) return;
    int d = i & (D_-1);
    int tok = i >> 9;
    int t = tok >> 6, n = tok & (N_-1);
    const float* f = xf + (size_t)tok*4;
    float acc = bx[d] + pe[t*D_ + d];
    #pragma unroll
    for (int k = 0; k < 4; k++) acc = fmaf(f[k], Wx[k*D_ + d], acc);
    xe[((size_t)(n*T_ + t))*D_ + d] = acc;
}

// writes ne fp32 (residual use) + split bf16 (GEMM A use)
__global__ void nemb_kernel(const float* __restrict__ nf, const float* __restrict__ Wn,
                            const float* __restrict__ bn, const float* __restrict__ pe,
                            float* __restrict__ ne, __nv_bfloat16* __restrict__ sp) {
    size_t i = (size_t)blockIdx.x * blockDim.x + threadIdx.x;
    if (i >= (size_t)NTOKB*D_) return;
    int d = (int)(i & (D_-1));
    int tok = (int)(i >> 9);
    int nn = tok & (NN_-1);
    int rem = tok >> 5;
    int n = rem & (N_-1);
    int t = rem >> 6;
    const float* f = nf + (size_t)tok*3;
    float acc = bn[d] + pe[t*D_ + d];
    acc = fmaf(f[0], Wn[d], acc);
    acc = fmaf(f[1], Wn[D_ + d], acc);
    acc = fmaf(f[2], Wn[2*D_ + d], acc);
    size_t row = (size_t)(n*NN_ + nn)*T_ + t;
    ne[row*D_ + d] = acc;
    splitw(sp, row*2*D_ + d, row*2*D_ + D_ + d, acc);
}

// ------------------------- neighbor attention --------------------------------
__global__ void attn_kernel(const float* __restrict__ QKV, const unsigned char* __restrict__ mask,
                            __nv_bfloat16* __restrict__ spCtx, float* __restrict__ attn_out) {
    int b = blockIdx.x;
    int h = b & (H_-1);
    int pair = b >> 3;
    int tid = threadIdx.x;
    __shared__ float q[16*68], k[16*68], v[16*68];
    __shared__ float at[16*17];
    size_t base = (size_t)pair*T_*1536 + h*DK_;
    for (int i = tid; i < 16*64; i += 256) {
        int t = i >> 6, d = i & 63;
        q[t*68+d] = QKV[base + (size_t)t*1536 + d];
        k[t*68+d] = QKV[base + (size_t)t*1536 + 512 + d];
        v[t*68+d] = QKV[base + (size_t)t*1536 + 1024 + d];
    }
    __syncthreads();
    int qt = tid >> 4, kt = tid & 15;
    float s = 0.0f;
    #pragma unroll
    for (int d = 0; d < 64; d++) s = fmaf(q[qt*68+d], k[kt*68+d], s);
    s *= 0.125f;
    if (!mask[pair*T_ + qt]) s = -1e9f;
    float mx = s;
    #pragma unroll
    for (int o = 8; o; o >>= 1) mx = fmaxf(mx, __shfl_xor_sync(0xffffffffu, mx, o));
    float e = expf(s - mx);
    float sum = e;
    #pragma unroll
    for (int o = 8; o; o >>= 1) sum += __shfl_xor_sync(0xffffffffu, sum, o);
    float a = e / sum;
    at[qt*17 + kt] = a;
    attn_out[(size_t)b*256 + qt*16 + kt] = a;
    __syncthreads();
    for (int i = tid; i < 16*64; i += 256) {
        int t = i >> 6, d = i & 63;
        float acc = 0.0f;
        #pragma unroll
        for (int kk = 0; kk < 16; kk++) acc = fmaf(at[t*17+kk], v[kk*68+d], acc);
        size_t row = (size_t)pair*T_ + t;
        splitw(spCtx, row*1024 + h*DK_ + d, row*1024 + 512 + h*DK_ + d, acc);
    }
}

__global__ void attmean_kernel(const float* __restrict__ attn, float* __restrict__ attint) {
    int i = blockIdx.x * blockDim.x + threadIdx.x;
    if (i >= N_*H_*256) return;
    int qk = i & 255;
    int h  = (i >> 8) & (H_-1);
    int n  = i >> 11;
    float s = 0.0f;
    #pragma unroll 4
    for (int nn = 0; nn < NN_; nn++)
        s += attn[(((size_t)(n*NN_ + nn)*H_ + h)*256) + qk];
    attint[i] = s * (1.0f/32.0f);
}

// ------------------------- add + layernorm (optional split out) --------------
__global__ void add_ln_kernel(const float* __restrict__ X, const float* __restrict__ R,
                              const float* __restrict__ g, const float* __restrict__ b,
                              float* __restrict__ out, __nv_bfloat16* __restrict__ sp) {
    int row = blockIdx.x, tid = threadIdx.x;
    size_t off = (size_t)row*D_;
    float x0 = X[off+tid]     + R[off+tid];
    float x1 = X[off+256+tid] + R[off+256+tid];
    __shared__ float red[8], red2[8];
    float s = x0 + x1;
    #pragma unroll
    for (int o = 16; o; o >>= 1) s += __shfl_xor_sync(0xffffffffu, s, o);
    if ((tid & 31) == 0) red[tid >> 5] = s;
    __syncthreads();
    float tot = 0.0f;
    #pragma unroll
    for (int i = 0; i < 8; i++) tot += red[i];
    float m = tot * (1.0f/512.0f);
    float d0 = x0 - m, d1 = x1 - m;
    float vs = d0*d0 + d1*d1;
    #pragma unroll
    for (int o = 16; o; o >>= 1) vs += __shfl_xor_sync(0xffffffffu, vs, o);
    if ((tid & 31) == 0) red2[tid >> 5] = vs;
    __syncthreads();
    float vtot = 0.0f;
    #pragma unroll
    for (int i = 0; i < 8; i++) vtot += red2[i];
    float inv = 1.0f / sqrtf(vtot * (1.0f/512.0f) + 1e-5f);
    float o0 = d0*inv*g[tid]     + b[tid];
    float o1 = d1*inv*g[tid+256] + b[tid+256];
    out[off+tid]     = o0;
    out[off+256+tid] = o1;
    if (sp) {
        size_t sro = (size_t)row*1024;
        splitw(sp, sro + tid,       sro + 512 + tid,       o0);
        splitw(sp, sro + 256 + tid, sro + 768 + tid,       o1);
    }
}

// ------------------------- self attention ------------------------------------
__global__ void attself_kernel(const float* __restrict__ xe, float* __restrict__ attself) {
    int n = blockIdx.x;
    int tid = threadIdx.x;
    __shared__ float xs[16*516];
    for (int i = tid; i < 16*D_; i += 256) {
        int t = i >> 9, d = i & (D_-1);
        xs[t*516 + d] = xe[((size_t)(n*T_ + t))*D_ + d];
    }
    __syncthreads();
    int q = tid >> 4, k = tid & 15;
    float s = 0.0f;
    for (int d = 0; d < D_; d++) s = fmaf(xs[q*516+d], xs[k*516+d], s);
    s *= 0.04419417382415922f;
    float mx = s;
    #pragma unroll
    for (int o = 8; o; o >>= 1) mx = fmaxf(mx, __shfl_xor_sync(0xffffffffu, mx, o));
    float e = expf(s - mx);
    float sum = e;
    #pragma unroll
    for (int o = 8; o; o >>= 1) sum += __shfl_xor_sync(0xffffffffu, sum, o);
    attself[(size_t)n*256 + q*16 + k] = e / sum;
}

// ------------------------- si (split out, row stride 2*H*D) ------------------
__global__ void si_kernel(const float* __restrict__ xe, const float* __restrict__ attself,
                          const float* __restrict__ attint, const float* __restrict__ att_factor,
                          __nv_bfloat16* __restrict__ spSi) {
    int n = blockIdx.x >> 4;
    int q = blockIdx.x & 15;
    int tid = threadIdx.x;
    __shared__ float xs[16*512];
    __shared__ float arow[H_*16];
    float factor = att_factor[0];
    for (int i = tid; i < 16*D_; i += 512) xs[i] = xe[(size_t)n*T_*D_ + i];
    if (tid < H_*16) {
        int h = tid >> 4, t = tid & 15;
        arow[tid] = attself[(size_t)n*256 + q*16 + t]
                  + factor * attint[((n*H_ + h)*16 + q)*16 + t];
    }
    __syncthreads();
    int d = tid;
    size_t row = (size_t)(n*T_ + q);
    #pragma unroll
    for (int h = 0; h < H_; h++) {
        float acc = 0.0f;
        #pragma unroll
        for (int t = 0; t < 16; t++) acc = fmaf(arow[h*16+t], xs[t*512 + d], acc);
        splitw(spSi, row*8192 + h*D_ + d, row*8192 + 4096 + h*D_ + d, acc);
    }
}

// ------------------------- prediction head -----------------------------------
__global__ void pred_kernel(const float* __restrict__ xe, const float* __restrict__ Wp,
                            const float* __restrict__ bp, float* __restrict__ out) {
    int idx = blockIdx.x * blockDim.x + threadIdx.x;
    if (idx >= N_*T_*2) return;
    int c = idx & 1;
    int t = (idx >> 1) & 15;
    int n = idx >> 5;
    float acc = bp[c];
    const float* xr = xe + ((size_t)(n*T_ + t))*D_;
    for (int d = 0; d < D_; d++) acc = fmaf(xr[d], Wp[d*2 + c], acc);
    for (int p = 0; p < 20; p++)
        out[(((size_t)p*T_ + t)*N_ + n)*2 + c] = acc;
}

// ---------------------------------------------------------------------------
static inline void convB(const float* W, __nv_bfloat16* Bq, int K, int Nw, int ldB,
                         int Ls, int wstride, long dstride, int ncol_off) {
    convB_kernel<<<((long)K*Nw*Ls+255)/256, 256>>>(W, Bq, K, Nw, ldB, Ls, wstride,
                                                   dstride, ncol_off);
}
static inline void gemm3s(cudaStream_t st, const __nv_bfloat16* A, const __nv_bfloat16* Bq,
                          float* C, __nv_bfloat16* Csp,
                          int M, int N, int K, int flags) {
    dim3 grid(N/128, M/128);
    gemm3_kernel<<<grid, 256, GSMEM_BYTES, st>>>(A, Bq, C, Csp, M, N, K, flags);
}

extern "C" void kernel_launch(void* const* d_in, const int* in_sizes, int n_in,
                              void* d_out, int out_size) {
    const float* x        = (const float*)d_in[0];
    const float* neighbor = (const float*)d_in[1];
    const float* att_fac  = (const float*)d_in[2];
    const float* Wx       = (const float*)d_in[3];
    const float* bx       = (const float*)d_in[4];
    const float* Wn       = (const float*)d_in[5];
    const float* bn       = (const float*)d_in[6];
    const float* Wpred    = (const float*)d_in[7];
    const float* bpred    = (const float*)d_in[8];
    const float* WQ       = (const float*)d_in[9];
    const float* WK       = (const float*)d_in[10];
    const float* WV       = (const float*)d_in[11];
    const float* Wfc      = (const float*)d_in[12];
    const float* mha_g    = (const float*)d_in[13];
    const float* mha_b    = (const float*)d_in[14];
    const float* WSI      = (const float*)d_in[15];
    const float* ffs_w1   = (const float*)d_in[16];
    const float* ffs_w2   = (const float*)d_in[17];
    const float* ffs_g    = (const float*)d_in[18];
    const float* ffs_b    = (const float*)d_in[19];
    const float* ffi_w1   = (const float*)d_in[20];
    const float* ffi_w2   = (const float*)d_in[21];
    const float* ffi_g    = (const float*)d_in[22];
    const float* ffi_b    = (const float*)d_in[23];
    float* out = (float*)d_out;

    static float *pxf=0,*pnf=0,*ppe=0,*pxe=0,*pne=0,*pqkv=0,
                 *ptmpM=0,*pres=0,*pattn=0,*pattint=0,*pattself=0,
                 *pxnew=0,*ptmpS=0;
    static __nv_bfloat16 *pBw=0,*spNe=0,*spCtx=0,*spRes=0,*spHidM=0,
                         *spSi=0,*spXnew=0,*spHidS=0;
    static unsigned char* pmask=0;
    static cudaStream_t s2 = 0;
    static cudaEvent_t evFork[L_], evSi[L_], evDone;
    if (!pxf) {
        cudaGetSymbolAddress((void**)&pxf, g_xf);
        cudaGetSymbolAddress((void**)&pnf, g_nf);
        cudaGetSymbolAddress((void**)&pmask, g_mask);
        cudaGetSymbolAddress((void**)&ppe, g_pe);
        cudaGetSymbolAddress((void**)&pxe, g_xe);
        cudaGetSymbolAddress((void**)&pne, g_ne);
        cudaGetSymbolAddress((void**)&pqkv, g_QKV);
        cudaGetSymbolAddress((void**)&ptmpM, g_tmpM);
        cudaGetSymbolAddress((void**)&pres, g_res);
        cudaGetSymbolAddress((void**)&pattn, g_attn);
        cudaGetSymbolAddress((void**)&pattint, g_attint);
        cudaGetSymbolAddress((void**)&pattself, g_attself);
        cudaGetSymbolAddress((void**)&pxnew, g_xnew);
        cudaGetSymbolAddress((void**)&ptmpS, g_tmpS);
        cudaGetSymbolAddress((void**)&pBw, g_Bw);
        cudaGetSymbolAddress((void**)&spNe, g_spNe);
        cudaGetSymbolAddress((void**)&spCtx, g_spCtx);
        cudaGetSymbolAddress((void**)&spRes, g_spRes);
        cudaGetSymbolAddress((void**)&spHidM, g_spHidM);
        cudaGetSymbolAddress((void**)&spSi, g_spSi);
        cudaGetSymbolAddress((void**)&spXnew, g_spXnew);
        cudaGetSymbolAddress((void**)&spHidS, g_spHidS);
        cudaFuncSetAttribute(gemm3_kernel, cudaFuncAttributeMaxDynamicSharedMemorySize,
                             GSMEM_BYTES);
        cudaStreamCreateWithFlags(&s2, cudaStreamNonBlocking);
        for (int l = 0; l < L_; l++) {
            cudaEventCreateWithFlags(&evFork[l], cudaEventDisableTiming);
            cudaEventCreateWithFlags(&evSi[l],   cudaEventDisableTiming);
        }
        cudaEventCreateWithFlags(&evDone, cudaEventDisableTiming);
    }

    // convert all weights for both layers up front (batched over L)
    convB(WQ, pBw + WOFF_QKV,        D_, D_, 1536, L_, D_*D_, WSZ_LAYER, 0);
    convB(WK, pBw + WOFF_QKV,        D_, D_, 1536, L_, D_*D_, WSZ_LAYER, 512);
    convB(WV, pBw + WOFF_QKV,        D_, D_, 1536, L_, D_*D_, WSZ_LAYER, 1024);
    convB(Wfc, pBw + WOFF_FC,        D_, D_, D_,   L_, D_*D_, WSZ_LAYER, 0);
    convB(WSI, pBw + WOFF_SI,    H_*D_, D_, D_,    L_, H_*D_*D_, WSZ_LAYER, 0);
    convB(ffs_w1, pBw + WOFF_FS1,    D_, DFF_, DFF_, L_, D_*DFF_, WSZ_LAYER, 0);
    convB(ffs_w2, pBw + WOFF_FS2,  DFF_, D_, D_,   L_, DFF_*D_, WSZ_LAYER, 0);
    convB(ffi_w1, pBw + WOFF_FI1,    D_, DFF_, DFF_, L_, D_*DFF_, WSZ_LAYER, 0);
    convB(ffi_w2, pBw + WOFF_FI2,  DFF_, D_, D_,   L_, DFF_*D_, WSZ_LAYER, 0);

    feat_kernel<<<(T_*N_*NN_+255)/256, 256>>>(x, neighbor, pxf, pnf, pmask);
    pe_kernel<<<(T_*D_+255)/256, 256>>>(ppe);
    xemb_kernel<<<(NTOKS*D_+255)/256, 256>>>(pxf, Wx, bx, ppe, pxe);
    nemb_kernel<<<(int)(((size_t)NTOKB*D_+255)/256), 256>>>(pnf, Wn, bn, ppe, pne, spNe);

    for (int l = 0; l < L_; l++) {
        __nv_bfloat16* Bl = pBw + (size_t)l*WSZ_LAYER;

        gemm3s(0, spNe, Bl + WOFF_QKV, pqkv, 0, NTOKB, 3*D_, D_, GF_F32);

        attn_kernel<<<NPAIR*H_, 256>>>(pqkv, pmask, spCtx, pattn);
        // WAR: attmean(l) overwrites attint while si(l-1) on s2 may read it.
        if (l > 0) cudaStreamWaitEvent(0, evSi[l-1], 0);
        attmean_kernel<<<(N_*H_*256+255)/256, 256>>>(pattn, pattint);
        cudaEventRecord(evFork[l], 0);

        // ---- self branch on s2 (hidden under neighbor-branch GEMMs) ----
        cudaStreamWaitEvent(s2, evFork[l], 0);
        attself_kernel<<<N_, 256, 0, s2>>>(pxe, pattself);
        si_kernel<<<NTOKS, 512, 0, s2>>>(pxe, pattself, pattint, att_fac, spSi);
        cudaEventRecord(evSi[l], s2);
        gemm3s(s2, spSi, Bl + WOFF_SI, pxnew, spXnew, NTOKS, D_, H_*D_, GF_F32 | GF_SPLIT);
        gemm3s(s2, spXnew, Bl + WOFF_FS1, 0, spHidS, NTOKS, DFF_, D_, GF_RELU | GF_SPLIT);
        gemm3s(s2, spHidS, Bl + WOFF_FS2, ptmpS, 0, NTOKS, D_, DFF_, GF_F32);
        add_ln_kernel<<<NTOKS, 256, 0, s2>>>(ptmpS, pxnew, ffs_g + l*D_, ffs_b + l*D_, pxe, 0);
        if (l == L_-1) cudaEventRecord(evDone, s2);

        // ---- neighbor branch on default stream ----
        gemm3s(0, spCtx, Bl + WOFF_FC, ptmpM, 0, NTOKB, D_, D_, GF_F32);
        add_ln_kernel<<<NTOKB, 256>>>(ptmpM, pne, mha_g + l*D_, mha_b + l*D_, pres, spRes);
        gemm3s(0, spRes, Bl + WOFF_FI1, 0, spHidM, NTOKB, DFF_, D_, GF_RELU | GF_SPLIT);
        gemm3s(0, spHidM, Bl + WOFF_FI2, ptmpM, 0, NTOKB, D_, DFF_, GF_F32);
        add_ln_kernel<<<NTOKB, 256>>>(ptmpM, pres, ffi_g + l*D_, ffi_b + l*D_, pne,
                                      (l+1 < L_) ? spNe : 0);
    }

    cudaStreamWaitEvent(0, evDone, 0);
    pred_kernel<<<(N_*T_*2+255)/256, 256>>>(pxe, Wpred, bpred, out);
}